// round 1
// baseline (speedup 1.0000x reference)
#include <cuda_runtime.h>

#define NN 100000
#define DD 16
#define HH 128
#define LL 2
#define CC 10

// ---------------- device scratch (no allocations allowed) ----------------
__device__ float g_h [NN*HH];          // layer-0 output h
__device__ float g_hs[NN*HH];          // LSTM hidden state / MLP ping
__device__ float g_cs[NN*HH];          // LSTM cell state  / MLP pong
__device__ float g_BtL[LL*256*512];    // lstm B transposed: [l][k][n]  (k<128: Wih, else Whh)
__device__ float g_BtS[LL*256*128];    // sage B transposed: [l][k][j]  (k<128: Wself, else Wneigh)
__device__ float g_bS [LL*128];        // bself + bneigh
__device__ float g_BtM[10*128*128];    // mlp  B transposed: [head][k][j], heads 0..4 cls, 5..9 cnf

// ---------------- helpers ----------------
__device__ __forceinline__ unsigned long long pack2(float x){
    unsigned long long r; unsigned u = __float_as_uint(x);
    asm("mov.b64 %0, {%1, %1};" : "=l"(r) : "r"(u));
    return r;
}
__device__ __forceinline__ void fma2(unsigned long long &d, unsigned long long a, unsigned long long b){
    asm("fma.rn.f32x2 %0, %1, %2, %0;" : "+l"(d) : "l"(a), "l"(b));
}
__device__ __forceinline__ float2 up2(unsigned long long v){
    return make_float2(__uint_as_float((unsigned)v), __uint_as_float((unsigned)(v >> 32)));
}
__device__ __forceinline__ float sigf(float x){ return 1.f/(1.f + __expf(-x)); }

// ---------------- prep kernels: weight transposes ----------------
__global__ void prep_lstm_kernel(const float* __restrict__ Wih, const float* __restrict__ Whh,
                                 float* __restrict__ Bt){
    int idx = blockIdx.x*blockDim.x + threadIdx.x;
    if (idx >= LL*256*512) return;
    int n = idx & 511;
    int k = (idx >> 9) & 255;
    int l = idx >> 17;
    float v = (k < 128) ? Wih[(l*512 + n)*128 + k]
                        : Whh[(l*512 + n)*128 + (k-128)];
    Bt[idx] = v;
}
__global__ void prep_sage_kernel(const float* __restrict__ Ws, const float* __restrict__ Wn,
                                 float* __restrict__ Bt){
    int idx = blockIdx.x*blockDim.x + threadIdx.x;
    if (idx >= LL*256*128) return;
    int j = idx & 127;
    int k = (idx >> 7) & 255;
    int l = idx >> 15;
    float v = (k < 128) ? Ws[(l*128 + j)*128 + k]
                        : Wn[(l*128 + j)*128 + (k-128)];
    Bt[idx] = v;
}
__global__ void prep_bias_kernel(const float* __restrict__ bs, const float* __restrict__ bn,
                                 float* __restrict__ bS){
    int idx = threadIdx.x;
    if (idx < LL*128) bS[idx] = bs[idx] + bn[idx];
}
__global__ void prep_mlp_kernel(const float* __restrict__ clsW, const float* __restrict__ cnfW,
                                float* __restrict__ Bt){
    int idx = blockIdx.x*blockDim.x + threadIdx.x;
    if (idx >= 10*128*128) return;
    int j = idx & 127;
    int k = (idx >> 7) & 127;
    int hd = idx >> 14;
    const float* W = (hd < 5) ? (clsW + hd*16384) : (cnfW + (hd-5)*16384);
    Bt[idx] = W[j*128 + k];
}

// ---------------- fused LSTM step: gates GEMM + pointwise update ----------------
// gates[N,512] = [x | hs] @ [Wih;Whh]^T ; i,f,g,o update fused. BM=32 nodes, full 512 cols/CTA.
// Thread owns 8 rows x (2 cols in each of the 4 gate blocks) so i/f/g/o are register-local.
__global__ void __launch_bounds__(256, 2) lstm_step_kernel(
    const float* __restrict__ hsrc, const int* __restrict__ nbr, int t,
    const float* __restrict__ Bt,   // [256][512]
    const float* __restrict__ bias, // [512]
    float* __restrict__ hs, float* __restrict__ cs, int first)
{
    __shared__ __align__(16) float Bs[16*512];
    __shared__ __align__(16) float As[16*32];
    __shared__ int s_idx[32];

    int tid = threadIdx.x;
    int block_row = blockIdx.x * 32;
    if (tid < 32) s_idx[tid] = nbr[(block_row + tid)*DD + t];

    unsigned long long acc[8][4];
#pragma unroll
    for (int i = 0; i < 8; i++){ acc[i][0]=0ull; acc[i][1]=0ull; acc[i][2]=0ull; acc[i][3]=0ull; }

    int tr = tid >> 6;        // 0..3 : row group of 8
    int tc = tid & 63;        // 0..63: col pair
    int jj = tc * 2;
    int Ktot = first ? 128 : 256;

    for (int k0 = 0; k0 < Ktot; k0 += 16){
        __syncthreads();
        // B tile 16x512 (contiguous in Bt)
        const float4* Bg = (const float4*)(Bt + k0*512);
        float4* Bs4 = (float4*)Bs;
#pragma unroll
        for (int i = 0; i < 8; i++) Bs4[tid + i*256] = Bg[tid + i*256];
        // A tile 16x32 transposed: k<128 gather from hsrc, else hs (own rows only)
        if (tid < 128){
            int m  = tid >> 2;
            int kq = (tid & 3) * 4;
            int krow = k0 + kq;
            float4 v;
            if (krow < 128)
                v = *(const float4*)(hsrc + (long)s_idx[m]*HH + krow);
            else
                v = *(const float4*)(hs + (long)(block_row + m)*HH + (krow - 128));
            As[(kq+0)*32 + m] = v.x;
            As[(kq+1)*32 + m] = v.y;
            As[(kq+2)*32 + m] = v.z;
            As[(kq+3)*32 + m] = v.w;
        }
        __syncthreads();
#pragma unroll
        for (int k = 0; k < 16; k++){
            const float* Ak = As + k*32 + tr*8;
            float4 a0 = *(const float4*)Ak;
            float4 a1 = *(const float4*)(Ak + 4);
            const float* Bk = Bs + k*512;
            unsigned long long b0 = *(const unsigned long long*)(Bk + jj);
            unsigned long long b1 = *(const unsigned long long*)(Bk + 128 + jj);
            unsigned long long b2 = *(const unsigned long long*)(Bk + 256 + jj);
            unsigned long long b3 = *(const unsigned long long*)(Bk + 384 + jj);
            float av[8] = {a0.x,a0.y,a0.z,a0.w,a1.x,a1.y,a1.z,a1.w};
#pragma unroll
            for (int i = 0; i < 8; i++){
                unsigned long long ap = pack2(av[i]);
                fma2(acc[i][0], ap, b0);
                fma2(acc[i][1], ap, b1);
                fma2(acc[i][2], ap, b2);
                fma2(acc[i][3], ap, b3);
            }
        }
    }
    // pointwise LSTM update (PyTorch gate order i,f,g,o)
    float2 bi = *(const float2*)(bias + jj);
    float2 bf = *(const float2*)(bias + 128 + jj);
    float2 bg = *(const float2*)(bias + 256 + jj);
    float2 bo = *(const float2*)(bias + 384 + jj);
#pragma unroll
    for (int i = 0; i < 8; i++){
        int row = block_row + tr*8 + i;
        long off = (long)row*HH + jj;
        float2 I = up2(acc[i][0]);
        float2 F = up2(acc[i][1]);
        float2 G = up2(acc[i][2]);
        float2 O = up2(acc[i][3]);
        I.x += bi.x; I.y += bi.y;
        F.x += bf.x; F.y += bf.y;
        G.x += bg.x; G.y += bg.y;
        O.x += bo.x; O.y += bo.y;
        float cx, cy;
        if (first){
            cx = sigf(I.x) * tanhf(G.x);
            cy = sigf(I.y) * tanhf(G.y);
        } else {
            float2 cold = *(const float2*)(cs + off);
            cx = sigf(F.x)*cold.x + sigf(I.x)*tanhf(G.x);
            cy = sigf(F.y)*cold.y + sigf(I.y)*tanhf(G.y);
        }
        float hx = sigf(O.x) * tanhf(cx);
        float hy = sigf(O.y) * tanhf(cy);
        *(float2*)(cs + off) = make_float2(cx, cy);
        *(float2*)(hs + off) = make_float2(hx, hy);
    }
}

// ---------------- generic GEMM [N,Ktot] @ Bt[Ktot][128] + bias (+relu) ----------------
// A = [A0 | A1] split at k=128. BM=64, BN=128, BK=16, 256 threads, 8x4 per thread.
__global__ void __launch_bounds__(256) gemm_bias_act_kernel(
    const float* __restrict__ A0, const float* __restrict__ A1,
    const float* __restrict__ Bt, const float* __restrict__ bias,
    float* __restrict__ Cout, int Ktot, int doRelu)
{
    __shared__ __align__(16) float Bs[16*128];
    __shared__ __align__(16) float As[16*64];
    int tid = threadIdx.x;
    int block_row = blockIdx.x * 64;
    int tr = tid >> 5;    // 0..7 rows group
    int tc = tid & 31;    // 0..31 col group of 4
    float acc[8][4];
#pragma unroll
    for (int i = 0; i < 8; i++){ acc[i][0]=0.f; acc[i][1]=0.f; acc[i][2]=0.f; acc[i][3]=0.f; }

    for (int k0 = 0; k0 < Ktot; k0 += 16){
        __syncthreads();
        const float4* Bg = (const float4*)(Bt + k0*128);
        float4* Bs4 = (float4*)Bs;
        Bs4[tid]       = Bg[tid];
        Bs4[tid + 256] = Bg[tid + 256];
        {
            int m  = tid >> 2;
            int kq = (tid & 3) * 4;
            int krow = k0 + kq;
            int row = block_row + m;
            float4 v = make_float4(0.f, 0.f, 0.f, 0.f);
            if (row < NN){
                const float* src = (krow < 128) ? (A0 + (long)row*HH + krow)
                                                : (A1 + (long)row*HH + (krow - 128));
                v = *(const float4*)src;
            }
            As[(kq+0)*64 + m] = v.x;
            As[(kq+1)*64 + m] = v.y;
            As[(kq+2)*64 + m] = v.z;
            As[(kq+3)*64 + m] = v.w;
        }
        __syncthreads();
#pragma unroll
        for (int k = 0; k < 16; k++){
            const float* Ak = As + k*64 + tr*8;
            float4 a0 = *(const float4*)Ak;
            float4 a1 = *(const float4*)(Ak + 4);
            float4 bv = *(const float4*)(Bs + k*128 + tc*4);
            float av[8] = {a0.x,a0.y,a0.z,a0.w,a1.x,a1.y,a1.z,a1.w};
            float bw[4] = {bv.x,bv.y,bv.z,bv.w};
#pragma unroll
            for (int i = 0; i < 8; i++)
#pragma unroll
                for (int j = 0; j < 4; j++)
                    acc[i][j] = fmaf(av[i], bw[j], acc[i][j]);
        }
    }
    float4 bb = *(const float4*)(bias + tc*4);
    float bbv[4] = {bb.x, bb.y, bb.z, bb.w};
#pragma unroll
    for (int i = 0; i < 8; i++){
        int row = block_row + tr*8 + i;
        if (row < NN){
            float4 o;
            float v0 = acc[i][0] + bbv[0];
            float v1 = acc[i][1] + bbv[1];
            float v2 = acc[i][2] + bbv[2];
            float v3 = acc[i][3] + bbv[3];
            if (doRelu){ v0 = fmaxf(v0,0.f); v1 = fmaxf(v1,0.f); v2 = fmaxf(v2,0.f); v3 = fmaxf(v3,0.f); }
            o.x=v0; o.y=v1; o.z=v2; o.w=v3;
            *(float4*)(Cout + (long)row*HH + tc*4) = o;
        }
    }
}

// ---------------- small output heads: out[n,c] = x[n,:] . W[c,:] + b[c] ----------------
__global__ void head_out_kernel(const float* __restrict__ x, const float* __restrict__ W,
                                const float* __restrict__ b, float* __restrict__ out, int Cn)
{
    int gwarp = (blockIdx.x * blockDim.x + threadIdx.x) >> 5;
    int lane  = threadIdx.x & 31;
    if (gwarp >= NN) return;
    const float* xr = x + (long)gwarp*HH;
    float x0 = xr[lane], x1 = xr[32+lane], x2 = xr[64+lane], x3 = xr[96+lane];
    for (int c = 0; c < Cn; c++){
        const float* w = W + c*HH;
        float s = x0*w[lane] + x1*w[32+lane] + x2*w[64+lane] + x3*w[96+lane];
        s += __shfl_xor_sync(0xffffffffu, s, 16);
        s += __shfl_xor_sync(0xffffffffu, s, 8);
        s += __shfl_xor_sync(0xffffffffu, s, 4);
        s += __shfl_xor_sync(0xffffffffu, s, 2);
        s += __shfl_xor_sync(0xffffffffu, s, 1);
        if (lane == 0) out[(long)gwarp*Cn + c] = s + b[c];
    }
}

// ---------------- launch ----------------
extern "C" void kernel_launch(void* const* d_in, const int* in_sizes, int n_in,
                              void* d_out, int out_size)
{
    const float* h_in   = (const float*)d_in[0];
    const int*   nbr    = (const int*)  d_in[1];
    const float* Wih    = (const float*)d_in[2];
    const float* Whh    = (const float*)d_in[3];
    const float* lstmb  = (const float*)d_in[4];
    const float* Wself  = (const float*)d_in[5];
    const float* bself  = (const float*)d_in[6];
    const float* Wneigh = (const float*)d_in[7];
    const float* bneigh = (const float*)d_in[8];
    const float* clsW   = (const float*)d_in[9];
    const float* clsb   = (const float*)d_in[10];
    const float* clsoW  = (const float*)d_in[11];
    const float* clsob  = (const float*)d_in[12];
    const float* cnfW   = (const float*)d_in[13];
    const float* cnfb   = (const float*)d_in[14];
    const float* cnfoW  = (const float*)d_in[15];
    const float* cnfob  = (const float*)d_in[16];

    float *p_h, *p_hs, *p_cs, *p_BtL, *p_BtS, *p_bS, *p_BtM;
    cudaGetSymbolAddress((void**)&p_h,   g_h);
    cudaGetSymbolAddress((void**)&p_hs,  g_hs);
    cudaGetSymbolAddress((void**)&p_cs,  g_cs);
    cudaGetSymbolAddress((void**)&p_BtL, g_BtL);
    cudaGetSymbolAddress((void**)&p_BtS, g_BtS);
    cudaGetSymbolAddress((void**)&p_bS,  g_bS);
    cudaGetSymbolAddress((void**)&p_BtM, g_BtM);

    float* out   = (float*)d_out;
    float* o_out = out;                                    // [N, 10]
    float* h_out = out + (size_t)NN*CC;                    // [N, 128]
    float* l_out = out + (size_t)NN*CC + (size_t)NN*HH;    // [N, 1]

    // weight transposes
    prep_lstm_kernel<<<(LL*256*512 + 255)/256, 256>>>(Wih, Whh, p_BtL);
    prep_sage_kernel<<<(LL*256*128 + 255)/256, 256>>>(Wself, Wneigh, p_BtS);
    prep_bias_kernel<<<1, 256>>>(bself, bneigh, p_bS);
    prep_mlp_kernel<<<(10*128*128 + 255)/256, 256>>>(clsW, cnfW, p_BtM);

    const int gemm_grid = (NN + 63) / 64;
    const float* hcur = h_in;
    for (int layer = 0; layer < LL; layer++){
        for (int t = 0; t < DD; t++){
            lstm_step_kernel<<<NN/32, 256>>>(hcur, nbr, t,
                p_BtL + layer*256*512, lstmb + layer*512, p_hs, p_cs, (t == 0) ? 1 : 0);
        }
        float* dst = (layer == 0) ? p_h : h_out;
        gemm_bias_act_kernel<<<gemm_grid, 256>>>(hcur, p_hs,
            p_BtS + layer*256*128, p_bS + layer*128, dst, 256, 1);
        hcur = dst;
    }

    // classification head: 5x (Linear+ReLU) then Linear H->10
    gemm_bias_act_kernel<<<gemm_grid, 256>>>(h_out, nullptr, p_BtM + 0*16384, clsb + 0*128, p_hs, 128, 1);
    gemm_bias_act_kernel<<<gemm_grid, 256>>>(p_hs,  nullptr, p_BtM + 1*16384, clsb + 1*128, p_cs, 128, 1);
    gemm_bias_act_kernel<<<gemm_grid, 256>>>(p_cs,  nullptr, p_BtM + 2*16384, clsb + 2*128, p_hs, 128, 1);
    gemm_bias_act_kernel<<<gemm_grid, 256>>>(p_hs,  nullptr, p_BtM + 3*16384, clsb + 3*128, p_cs, 128, 1);
    gemm_bias_act_kernel<<<gemm_grid, 256>>>(p_cs,  nullptr, p_BtM + 4*16384, clsb + 4*128, p_hs, 128, 1);
    head_out_kernel<<<(NN*32 + 255)/256, 256>>>(p_hs, clsoW, clsob, o_out, CC);

    // confidence head: 5x (Linear+ReLU) then Linear H->1
    gemm_bias_act_kernel<<<gemm_grid, 256>>>(h_out, nullptr, p_BtM + 5*16384, cnfb + 0*128, p_hs, 128, 1);
    gemm_bias_act_kernel<<<gemm_grid, 256>>>(p_hs,  nullptr, p_BtM + 6*16384, cnfb + 1*128, p_cs, 128, 1);
    gemm_bias_act_kernel<<<gemm_grid, 256>>>(p_cs,  nullptr, p_BtM + 7*16384, cnfb + 2*128, p_hs, 128, 1);
    gemm_bias_act_kernel<<<gemm_grid, 256>>>(p_hs,  nullptr, p_BtM + 8*16384, cnfb + 3*128, p_cs, 128, 1);
    gemm_bias_act_kernel<<<gemm_grid, 256>>>(p_cs,  nullptr, p_BtM + 9*16384, cnfb + 4*128, p_hs, 128, 1);
    head_out_kernel<<<(NN*32 + 255)/256, 256>>>(p_hs, cnfoW, cnfob, l_out, 1);
}

// round 3
// speedup vs baseline: 1.0049x; 1.0049x over previous
#include <cuda_runtime.h>
#include <cuda_bf16.h>
#include <cstdint>

#define NN 100000
#define DD 16
#define HH 128
#define LL 2
#define CC 10
#define NBLK 782        // ceil(100000/128)
#define GRID_TC 148
#define CSTR 37         // node-block stride (148/4 gate tiles)

// ---------------- device scratch ----------------
__device__ float g_h  [NN*HH];
__device__ float g_hs [NN*HH];
__device__ float g_hs2[NN*HH];
__device__ float g_cs [NN*HH];
__device__ __nv_bfloat16 g_Bimg[LL*4*65536];    // [l][gate_tile][hi 64KB | lo 64KB] smem-layout image
__device__ float g_bimg[LL*4*128];              // gate-interleaved lstm bias per tile
__device__ float g_BtS[LL*256*128];
__device__ float g_bS [LL*128];
__device__ float g_BtM[10*128*128];

// ---------------- helpers ----------------
__device__ __forceinline__ uint32_t smem_u32(const void* p){
    uint32_t a;
    asm("{ .reg .u64 t; cvta.to.shared.u64 t, %1; cvt.u32.u64 %0, t; }" : "=r"(a) : "l"(p));
    return a;
}
__device__ __forceinline__ void ldsm4(uint32_t* r, uint32_t addr){
    asm volatile("ldmatrix.sync.aligned.m8n8.x4.shared.b16 {%0,%1,%2,%3}, [%4];"
        : "=r"(r[0]), "=r"(r[1]), "=r"(r[2]), "=r"(r[3]) : "r"(addr));
}
__device__ __forceinline__ void ldsm2(uint32_t* r, uint32_t addr){
    asm volatile("ldmatrix.sync.aligned.m8n8.x2.shared.b16 {%0,%1}, [%2];"
        : "=r"(r[0]), "=r"(r[1]) : "r"(addr));
}
__device__ __forceinline__ void mma_bf16(float* c, const uint32_t* a, const uint32_t* b){
    asm volatile("mma.sync.aligned.m16n8k16.row.col.f32.bf16.bf16.f32 "
        "{%0,%1,%2,%3}, {%4,%5,%6,%7}, {%8,%9}, {%0,%1,%2,%3};"
        : "+f"(c[0]), "+f"(c[1]), "+f"(c[2]), "+f"(c[3])
        : "r"(a[0]), "r"(a[1]), "r"(a[2]), "r"(a[3]), "r"(b[0]), "r"(b[1]));
}
__device__ __forceinline__ uint32_t b2u(__nv_bfloat162 v){ return *(uint32_t*)&v; }
__device__ __forceinline__ float sigf(float x){ return 1.f/(1.f + __expf(-x)); }

// ---------------- prep: swizzled gate-interleaved bf16 hi/lo B image ----------------
// smem layout per (l,gt) tile: B_hi[j][k] then B_lo: row = 512B (k=256 bf16),
// byte off = j*512 + ((k*2) ^ ((j&7)<<4)). Gate-interleaved col j -> original col oc.
__global__ void prep_lstm_img(const float* __restrict__ Wih, const float* __restrict__ Whh,
                              const float* __restrict__ b,
                              __nv_bfloat16* __restrict__ Bimg, float* __restrict__ bimg){
    int idx = blockIdx.x*blockDim.x + threadIdx.x;
    if (idx >= LL*4*128*256) return;
    int k  = idx & 255;
    int j  = (idx >> 8) & 127;
    int gt = (idx >> 15) & 3;
    int l  = idx >> 17;
    int oc = (j & 3)*128 + gt*32 + (j >> 2);
    float w = (k < 128) ? Wih[(l*512 + oc)*128 + k]
                        : Whh[(l*512 + oc)*128 + (k-128)];
    __nv_bfloat16 hi = __float2bfloat16(w);
    __nv_bfloat16 lo = __float2bfloat16(w - __bfloat162float(hi));
    uint32_t boff = (uint32_t)j*512u + (((uint32_t)k*2u) ^ (((uint32_t)j & 7u) << 4));
    size_t tile = (size_t)(l*4 + gt) * 65536;
    Bimg[tile + (boff >> 1)]         = hi;
    Bimg[tile + 32768 + (boff >> 1)] = lo;
    if (k == 0) bimg[(l*4 + gt)*128 + j] = b[l*512 + oc];
}

__global__ void prep_sage_kernel(const float* __restrict__ Ws, const float* __restrict__ Wn,
                                 float* __restrict__ Bt){
    int idx = blockIdx.x*blockDim.x + threadIdx.x;
    if (idx >= LL*256*128) return;
    int j = idx & 127;
    int k = (idx >> 7) & 255;
    int l = idx >> 15;
    float v = (k < 128) ? Ws[(l*128 + j)*128 + k] : Wn[(l*128 + j)*128 + (k-128)];
    Bt[idx] = v;
}
__global__ void prep_bias_kernel(const float* __restrict__ bs, const float* __restrict__ bn,
                                 float* __restrict__ bS){
    int idx = threadIdx.x;
    if (idx < LL*128) bS[idx] = bs[idx] + bn[idx];
}
__global__ void prep_mlp_kernel(const float* __restrict__ clsW, const float* __restrict__ cnfW,
                                float* __restrict__ Bt){
    int idx = blockIdx.x*blockDim.x + threadIdx.x;
    if (idx >= 10*128*128) return;
    int j = idx & 127;
    int k = (idx >> 7) & 127;
    int hd = idx >> 14;
    const float* W = (hd < 5) ? (clsW + hd*16384) : (cnfW + (hd-5)*16384);
    Bt[idx] = W[j*128 + k];
}

// ---------------- LSTM step via mma.sync bf16x3 ----------------
// grid = 148 persistent CTAs: gt = bid&3 (gate tile), cidx = bid>>2; loop node-blocks of 128.
// smem: A_hi[128][128]bf16 (32KB) | A_lo (32KB) | B_hi[128][256]bf16 (64KB) | B_lo (64KB) | bias (512B)
#define SA_HI 0
#define SA_LO 32768
#define SB_HI 65536
#define SB_LO 131072
#define SBIAS 196608
#define SMEM_TC 197120

__global__ void __launch_bounds__(256, 1) lstm_step_mma(
    const float* __restrict__ hsrc, const int* __restrict__ nbr,
    int t, int layer, int first,
    const __nv_bfloat16* __restrict__ Bimg, const float* __restrict__ bimg,
    const float* __restrict__ hs_in, float* __restrict__ hs_out,
    float* __restrict__ cs)
{
    extern __shared__ __align__(16) char smem[];
    const int tid  = threadIdx.x;
    const int lane = tid & 31;
    const int wid  = tid >> 5;
    const int wm   = wid & 1;     // m half: rows wm*64..+63
    const int wn   = wid >> 1;    // n quarter: interleaved cols wn*32..+31
    const int gt   = blockIdx.x & 3;
    const int cidx = blockIdx.x >> 2;

    const uint32_t sbase = smem_u32(smem);
    float* bias_s = (float*)(smem + SBIAS);

    // load B tile (hi+lo, 128KB) and bias once
    {
        const int4* src = (const int4*)(Bimg + (size_t)(layer*4 + gt) * 65536);
        int4* dst = (int4*)(smem + SB_HI);
        #pragma unroll 8
        for (int i = tid; i < 8192; i += 256) dst[i] = src[i];
        if (tid < 128) bias_s[tid] = bimg[(layer*4 + gt)*128 + tid];
    }

    for (int nb = cidx; nb < NBLK; nb += CSTR){
        const int nbbase = nb * 128;
        float c[4][4][4];
        #pragma unroll
        for (int a = 0; a < 4; a++)
            #pragma unroll
            for (int b = 0; b < 4; b++){
                c[a][b][0]=0.f; c[a][b][1]=0.f; c[a][b][2]=0.f; c[a][b][3]=0.f;
            }

        // two K-halves: 0 = x (gather via nbr), 1 = hs (skipped when first)
        const int nhalf = first ? 1 : 2;
        for (int hidx = 0; hidx < nhalf; hidx++){
            __syncthreads();   // A buffer free (prev MMA reads done)
            // ---- stage A half: 2 threads per row, 64 floats each ----
            {
                int m   = tid >> 1;
                int seg = (tid & 1) * 64;
                int node = nbbase + m;
                if (node >= NN) node = NN - 1;
                const float* rowp;
                if (hidx == 0) rowp = hsrc  + (size_t)__ldg(&nbr[node*DD + t]) * HH + seg;
                else           rowp = hs_in + (size_t)node * HH + seg;
                char* hiB = smem + SA_HI + m*256;
                char* loB = smem + SA_LO + m*256;
                const uint32_t swm = ((uint32_t)m & 7u) << 4;
                #pragma unroll
                for (int q = 0; q < 16; q++){
                    float4 v = __ldg((const float4*)rowp + q);
                    __nv_bfloat162 h0 = __floats2bfloat162_rn(v.x, v.y);
                    __nv_bfloat162 h1 = __floats2bfloat162_rn(v.z, v.w);
                    float2 f0 = __bfloat1622float2(h0);
                    float2 f1 = __bfloat1622float2(h1);
                    __nv_bfloat162 l0 = __floats2bfloat162_rn(v.x - f0.x, v.y - f0.y);
                    __nv_bfloat162 l1 = __floats2bfloat162_rn(v.z - f1.x, v.w - f1.y);
                    uint32_t off = (((uint32_t)(seg + q*4)) * 2u) ^ swm;
                    *(uint2*)(hiB + off) = make_uint2(b2u(h0), b2u(h1));
                    *(uint2*)(loB + off) = make_uint2(b2u(l0), b2u(l1));
                }
            }
            __syncthreads();
            // ---- MMA over this K-half ----
            const int ktg0 = hidx * 8;   // global B k-tile base
            const int sel  = lane >> 3;
            #pragma unroll
            for (int kt = 0; kt < 8; kt++){
                uint32_t ah[4][4], al[4][4];
                #pragma unroll
                for (int mi = 0; mi < 4; mi++){
                    int m = wm*64 + mi*16 + (sel & 1)*8 + (lane & 7);
                    uint32_t kb = (uint32_t)(kt*32 + (sel >> 1)*16);
                    uint32_t aoff = (uint32_t)m*256u + (kb ^ (((uint32_t)m & 7u) << 4));
                    ldsm4(ah[mi], sbase + SA_HI + aoff);
                    ldsm4(al[mi], sbase + SA_LO + aoff);
                }
                const int l2 = lane & 15;
                #pragma unroll
                for (int ni = 0; ni < 4; ni++){
                    int n = wn*32 + ni*8 + (l2 & 7);
                    uint32_t kb = (uint32_t)((ktg0 + kt)*32 + ((l2 >> 3) << 4));
                    uint32_t boff = (uint32_t)n*512u + (kb ^ (((uint32_t)n & 7u) << 4));
                    uint32_t bh[2], bl[2];
                    ldsm2(bh, sbase + SB_HI + boff);
                    ldsm2(bl, sbase + SB_LO + boff);
                    #pragma unroll
                    for (int mi = 0; mi < 4; mi++){
                        mma_bf16(c[mi][ni], ah[mi], bh);
                        mma_bf16(c[mi][ni], al[mi], bh);
                        mma_bf16(c[mi][ni], ah[mi], bl);
                    }
                }
            }
            __syncthreads();   // MMA reads done before next staging overwrites A
        }

        // ---- fused LSTM epilogue ----
        // lane pairs (l, l^1): even (lane&1==0) holds (i,f), odd holds (g,o) of same h-col.
        #pragma unroll
        for (int mi = 0; mi < 4; mi++){
            #pragma unroll
            for (int ni = 0; ni < 4; ni++){
                float* cc = c[mi][ni];
                int j0 = wn*32 + ni*8 + 2*(lane & 3);
                float b0 = bias_s[j0], b1 = bias_s[j0 + 1];
                cc[0] += b0; cc[1] += b1; cc[2] += b0; cc[3] += b1;
                float p0 = __shfl_xor_sync(0xffffffffu, cc[0], 1);
                float p1 = __shfl_xor_sync(0xffffffffu, cc[1], 1);
                float p2 = __shfl_xor_sync(0xffffffffu, cc[2], 1);
                float p3 = __shfl_xor_sync(0xffffffffu, cc[3], 1);
                if ((lane & 1) == 0){
                    int rloc = wm*64 + mi*16 + (lane >> 2);
                    int hc   = gt*32 + wn*8 + ni*2 + ((lane & 3) >> 1);
                    #pragma unroll
                    for (int rr = 0; rr < 2; rr++){
                        int node = nbbase + rloc + rr*8;
                        if (node < NN){
                            float I = (rr == 0) ? cc[0] : cc[2];
                            float F = (rr == 0) ? cc[1] : cc[3];
                            float G = (rr == 0) ? p0 : p2;
                            float O = (rr == 0) ? p1 : p3;
                            size_t idx = (size_t)node*HH + hc;
                            float cnew;
                            if (first) cnew = sigf(I)*tanhf(G);
                            else       cnew = sigf(F)*cs[idx] + sigf(I)*tanhf(G);
                            cs[idx]     = cnew;
                            hs_out[idx] = sigf(O)*tanhf(cnew);
                        }
                    }
                }
            }
        }
    }
}

// ---------------- fp32 GEMM [N,Ktot] @ Bt[Ktot][128] + bias (+relu) ----------------
__global__ void __launch_bounds__(256) gemm_bias_act_kernel(
    const float* __restrict__ A0, const float* __restrict__ A1,
    const float* __restrict__ Bt, const float* __restrict__ bias,
    float* __restrict__ Cout, int Ktot, int doRelu)
{
    __shared__ __align__(16) float Bs[16*128];
    __shared__ __align__(16) float As[16*64];
    int tid = threadIdx.x;
    int block_row = blockIdx.x * 64;
    int tr = tid >> 5;
    int tc = tid & 31;
    float acc[8][4];
#pragma unroll
    for (int i = 0; i < 8; i++){ acc[i][0]=0.f; acc[i][1]=0.f; acc[i][2]=0.f; acc[i][3]=0.f; }

    for (int k0 = 0; k0 < Ktot; k0 += 16){
        __syncthreads();
        const float4* Bg = (const float4*)(Bt + k0*128);
        float4* Bs4 = (float4*)Bs;
        Bs4[tid]       = Bg[tid];
        Bs4[tid + 256] = Bg[tid + 256];
        {
            int m  = tid >> 2;
            int kq = (tid & 3) * 4;
            int krow = k0 + kq;
            int row = block_row + m;
            float4 v = make_float4(0.f, 0.f, 0.f, 0.f);
            if (row < NN){
                const float* src = (krow < 128) ? (A0 + (size_t)row*HH + krow)
                                                : (A1 + (size_t)row*HH + (krow - 128));
                v = *(const float4*)src;
            }
            As[(kq+0)*64 + m] = v.x;
            As[(kq+1)*64 + m] = v.y;
            As[(kq+2)*64 + m] = v.z;
            As[(kq+3)*64 + m] = v.w;
        }
        __syncthreads();
#pragma unroll
        for (int k = 0; k < 16; k++){
            const float* Ak = As + k*64 + tr*8;
            float4 a0 = *(const float4*)Ak;
            float4 a1 = *(const float4*)(Ak + 4);
            float4 bv = *(const float4*)(Bs + k*128 + tc*4);
            float av[8] = {a0.x,a0.y,a0.z,a0.w,a1.x,a1.y,a1.z,a1.w};
            float bw[4] = {bv.x,bv.y,bv.z,bv.w};
#pragma unroll
            for (int i = 0; i < 8; i++)
#pragma unroll
                for (int j = 0; j < 4; j++)
                    acc[i][j] = fmaf(av[i], bw[j], acc[i][j]);
        }
    }
    float4 bb = *(const float4*)(bias + tc*4);
    float bbv[4] = {bb.x, bb.y, bb.z, bb.w};
#pragma unroll
    for (int i = 0; i < 8; i++){
        int row = block_row + tr*8 + i;
        if (row < NN){
            float4 o;
            float v0 = acc[i][0] + bbv[0];
            float v1 = acc[i][1] + bbv[1];
            float v2 = acc[i][2] + bbv[2];
            float v3 = acc[i][3] + bbv[3];
            if (doRelu){ v0=fmaxf(v0,0.f); v1=fmaxf(v1,0.f); v2=fmaxf(v2,0.f); v3=fmaxf(v3,0.f); }
            o.x=v0; o.y=v1; o.z=v2; o.w=v3;
            *(float4*)(Cout + (size_t)row*HH + tc*4) = o;
        }
    }
}

// ---------------- small output heads ----------------
__global__ void head_out_kernel(const float* __restrict__ x, const float* __restrict__ W,
                                const float* __restrict__ b, float* __restrict__ out, int Cn)
{
    int gwarp = (blockIdx.x * blockDim.x + threadIdx.x) >> 5;
    int lane  = threadIdx.x & 31;
    if (gwarp >= NN) return;
    const float* xr = x + (size_t)gwarp*HH;
    float x0 = xr[lane], x1 = xr[32+lane], x2 = xr[64+lane], x3 = xr[96+lane];
    for (int c = 0; c < Cn; c++){
        const float* w = W + c*HH;
        float s = x0*w[lane] + x1*w[32+lane] + x2*w[64+lane] + x3*w[96+lane];
        s += __shfl_xor_sync(0xffffffffu, s, 16);
        s += __shfl_xor_sync(0xffffffffu, s, 8);
        s += __shfl_xor_sync(0xffffffffu, s, 4);
        s += __shfl_xor_sync(0xffffffffu, s, 2);
        s += __shfl_xor_sync(0xffffffffu, s, 1);
        if (lane == 0) out[(size_t)gwarp*Cn + c] = s + b[c];
    }
}

// ---------------- launch ----------------
extern "C" void kernel_launch(void* const* d_in, const int* in_sizes, int n_in,
                              void* d_out, int out_size)
{
    const float* h_in   = (const float*)d_in[0];
    const int*   nbr    = (const int*)  d_in[1];
    const float* Wih    = (const float*)d_in[2];
    const float* Whh    = (const float*)d_in[3];
    const float* lstmb  = (const float*)d_in[4];
    const float* Wself  = (const float*)d_in[5];
    const float* bself  = (const float*)d_in[6];
    const float* Wneigh = (const float*)d_in[7];
    const float* bneigh = (const float*)d_in[8];
    const float* clsW   = (const float*)d_in[9];
    const float* clsb   = (const float*)d_in[10];
    const float* clsoW  = (const float*)d_in[11];
    const float* clsob  = (const float*)d_in[12];
    const float* cnfW   = (const float*)d_in[13];
    const float* cnfb   = (const float*)d_in[14];
    const float* cnfoW  = (const float*)d_in[15];
    const float* cnfob  = (const float*)d_in[16];

    float *p_h, *p_hs, *p_hs2, *p_cs, *p_bimg, *p_BtS, *p_bS, *p_BtM;
    __nv_bfloat16* p_Bimg;
    cudaGetSymbolAddress((void**)&p_h,    g_h);
    cudaGetSymbolAddress((void**)&p_hs,   g_hs);
    cudaGetSymbolAddress((void**)&p_hs2,  g_hs2);
    cudaGetSymbolAddress((void**)&p_cs,   g_cs);
    cudaGetSymbolAddress((void**)&p_Bimg, g_Bimg);
    cudaGetSymbolAddress((void**)&p_bimg, g_bimg);
    cudaGetSymbolAddress((void**)&p_BtS,  g_BtS);
    cudaGetSymbolAddress((void**)&p_bS,   g_bS);
    cudaGetSymbolAddress((void**)&p_BtM,  g_BtM);

    float* out   = (float*)d_out;
    float* o_out = out;
    float* h_out = out + (size_t)NN*CC;
    float* l_out = out + (size_t)NN*CC + (size_t)NN*HH;

    cudaFuncSetAttribute(lstm_step_mma, cudaFuncAttributeMaxDynamicSharedMemorySize, SMEM_TC);

    // preps
    prep_lstm_img<<<(LL*4*128*256 + 255)/256, 256>>>(Wih, Whh, lstmb, p_Bimg, p_bimg);
    prep_sage_kernel<<<(LL*256*128 + 255)/256, 256>>>(Wself, Wneigh, p_BtS);
    prep_bias_kernel<<<1, 256>>>(bself, bneigh, p_bS);
    prep_mlp_kernel<<<(10*128*128 + 255)/256, 256>>>(clsW, cnfW, p_BtM);

    const int gemm_grid = (NN + 63) / 64;
    const float* hcur = h_in;
    for (int layer = 0; layer < LL; layer++){
        for (int t = 0; t < DD; t++){
            float* hs_o = (t & 1) ? p_hs2 : p_hs;
            const float* hs_i = (t & 1) ? p_hs : p_hs2;
            lstm_step_mma<<<GRID_TC, 256, SMEM_TC>>>(hcur, nbr, t, layer, (t == 0) ? 1 : 0,
                                                     p_Bimg, p_bimg, hs_i, hs_o, p_cs);
        }
        // final step t=15 wrote p_hs2
        float* dst = (layer == 0) ? p_h : h_out;
        gemm_bias_act_kernel<<<gemm_grid, 256>>>(hcur, p_hs2,
            p_BtS + layer*256*128, p_bS + layer*128, dst, 256, 1);
        hcur = dst;
    }

    // classification head
    gemm_bias_act_kernel<<<gemm_grid, 256>>>(h_out, nullptr, p_BtM + 0*16384, clsb + 0*128, p_hs, 128, 1);
    gemm_bias_act_kernel<<<gemm_grid, 256>>>(p_hs,  nullptr, p_BtM + 1*16384, clsb + 1*128, p_cs, 128, 1);
    gemm_bias_act_kernel<<<gemm_grid, 256>>>(p_cs,  nullptr, p_BtM + 2*16384, clsb + 2*128, p_hs, 128, 1);
    gemm_bias_act_kernel<<<gemm_grid, 256>>>(p_hs,  nullptr, p_BtM + 3*16384, clsb + 3*128, p_cs, 128, 1);
    gemm_bias_act_kernel<<<gemm_grid, 256>>>(p_cs,  nullptr, p_BtM + 4*16384, clsb + 4*128, p_hs, 128, 1);
    head_out_kernel<<<(NN*32 + 255)/256, 256>>>(p_hs, clsoW, clsob, o_out, CC);

    // confidence head
    gemm_bias_act_kernel<<<gemm_grid, 256>>>(h_out, nullptr, p_BtM + 5*16384, cnfb + 0*128, p_hs, 128, 1);
    gemm_bias_act_kernel<<<gemm_grid, 256>>>(p_hs,  nullptr, p_BtM + 6*16384, cnfb + 1*128, p_cs, 128, 1);
    gemm_bias_act_kernel<<<gemm_grid, 256>>>(p_cs,  nullptr, p_BtM + 7*16384, cnfb + 2*128, p_hs, 128, 1);
    gemm_bias_act_kernel<<<gemm_grid, 256>>>(p_hs,  nullptr, p_BtM + 8*16384, cnfb + 3*128, p_cs, 128, 1);
    gemm_bias_act_kernel<<<gemm_grid, 256>>>(p_cs,  nullptr, p_BtM + 9*16384, cnfb + 4*128, p_hs, 128, 1);
    head_out_kernel<<<(NN*32 + 255)/256, 256>>>(p_hs, cnfoW, cnfob, l_out, 1);
}

// round 4
// speedup vs baseline: 1.6470x; 1.6390x over previous
#include <cuda_runtime.h>
#include <cstdint>

#define NN 100000
#define DD 16
#define HH 128
#define LL 2
#define CC 10

// ---------------- device scratch ----------------
__device__ float g_X  [(size_t)NN*512];   // precomputed x-side gates: X = h @ Wih^T + b  [node][512]
__device__ float g_h  [NN*HH];            // layer-0 sage output
__device__ float g_hs [NN*HH];            // hs ping
__device__ float g_hs2[NN*HH];            // hs pong
__device__ float g_cs [NN*HH];            // cell state
__device__ float g_BtX[LL*128*512];       // Wih^T  [l][k][n]
__device__ float g_BtH[LL*128*512];       // Whh^T  [l][k][n]
__device__ float g_BtS[LL*256*128];       // sage   [l][k][j] (k<128 Wself else Wneigh)
__device__ float g_bS [LL*128];           // bself + bneigh
__device__ float g_BtM[10*128*128];       // mlp heads transposed

// ---------------- helpers ----------------
__device__ __forceinline__ unsigned long long pack2(float x){
    unsigned long long r; unsigned u = __float_as_uint(x);
    asm("mov.b64 %0, {%1, %1};" : "=l"(r) : "r"(u));
    return r;
}
__device__ __forceinline__ void fma2(unsigned long long &d, unsigned long long a, unsigned long long b){
    asm("fma.rn.f32x2 %0, %1, %2, %0;" : "+l"(d) : "l"(a), "l"(b));
}
__device__ __forceinline__ float2 up2(unsigned long long v){
    return make_float2(__uint_as_float((unsigned)v), __uint_as_float((unsigned)(v >> 32)));
}
__device__ __forceinline__ float sigf(float x){ return 1.f/(1.f + __expf(-x)); }
__device__ __forceinline__ uint32_t smem_u32(const void* p){
    uint32_t a;
    asm("{ .reg .u64 t; cvta.to.shared.u64 t, %1; cvt.u32.u64 %0, t; }" : "=r"(a) : "l"(p));
    return a;
}
__device__ __forceinline__ void cp_async16(uint32_t dst, const void* src){
    asm volatile("cp.async.cg.shared.global [%0], [%1], 16;" :: "r"(dst), "l"(src));
}
#define CP_COMMIT() asm volatile("cp.async.commit_group;" ::: "memory")
#define CP_WAIT0()  asm volatile("cp.async.wait_group 0;" ::: "memory")

// ---------------- prep: weight transposes ----------------
__global__ void prep_lstm_t(const float* __restrict__ Wih, const float* __restrict__ Whh,
                            float* __restrict__ BtX, float* __restrict__ BtH){
    int idx = blockIdx.x*blockDim.x + threadIdx.x;
    if (idx >= LL*128*512) return;
    int n = idx & 511;
    int k = (idx >> 9) & 127;
    int l = idx >> 16;
    BtX[idx] = Wih[(l*512 + n)*128 + k];
    BtH[idx] = Whh[(l*512 + n)*128 + k];
}
__global__ void prep_sage_kernel(const float* __restrict__ Ws, const float* __restrict__ Wn,
                                 float* __restrict__ Bt){
    int idx = blockIdx.x*blockDim.x + threadIdx.x;
    if (idx >= LL*256*128) return;
    int j = idx & 127;
    int k = (idx >> 7) & 255;
    int l = idx >> 15;
    Bt[idx] = (k < 128) ? Ws[(l*128 + j)*128 + k] : Wn[(l*128 + j)*128 + (k-128)];
}
__global__ void prep_bias_kernel(const float* __restrict__ bs, const float* __restrict__ bn,
                                 float* __restrict__ bS){
    int idx = threadIdx.x;
    if (idx < LL*128) bS[idx] = bs[idx] + bn[idx];
}
__global__ void prep_mlp_kernel(const float* __restrict__ clsW, const float* __restrict__ cnfW,
                                float* __restrict__ Bt){
    int idx = blockIdx.x*blockDim.x + threadIdx.x;
    if (idx >= 10*128*128) return;
    int j = idx & 127;
    int k = (idx >> 7) & 127;
    int hd = idx >> 14;
    const float* W = (hd < 5) ? (clsW + hd*16384) : (cnfW + (hd-5)*16384);
    Bt[idx] = W[j*128 + k];
}

// ---------------- precompute X = h @ Wih^T + b : [N,128]@[128,512] ----------------
// BM=32, 512 cols/CTA, 256 threads, packed-f32x2 FMA. Thread owns 8 rows x (2 cols in 4 gate blocks).
__global__ void __launch_bounds__(256, 2) precompute_x_kernel(
    const float* __restrict__ hsrc, const float* __restrict__ Bt,  // [128][512]
    const float* __restrict__ bias, float* __restrict__ X)
{
    __shared__ __align__(16) float Bs[16*512];
    __shared__ __align__(16) float As[16*32];
    int tid = threadIdx.x;
    int block_row = blockIdx.x * 32;

    unsigned long long acc[8][4];
#pragma unroll
    for (int i = 0; i < 8; i++){ acc[i][0]=0ull; acc[i][1]=0ull; acc[i][2]=0ull; acc[i][3]=0ull; }

    int tr = tid >> 6;
    int tc = tid & 63;
    int jj = tc * 2;

    for (int k0 = 0; k0 < 128; k0 += 16){
        __syncthreads();
        const float4* Bg = (const float4*)(Bt + k0*512);
        float4* Bs4 = (float4*)Bs;
#pragma unroll
        for (int i = 0; i < 8; i++) Bs4[tid + i*256] = Bg[tid + i*256];
        if (tid < 128){
            int m  = tid >> 2;
            int kq = (tid & 3) * 4;
            float4 v = *(const float4*)(hsrc + (size_t)(block_row + m)*HH + k0 + kq);
            As[(kq+0)*32 + m] = v.x;
            As[(kq+1)*32 + m] = v.y;
            As[(kq+2)*32 + m] = v.z;
            As[(kq+3)*32 + m] = v.w;
        }
        __syncthreads();
#pragma unroll
        for (int k = 0; k < 16; k++){
            const float* Ak = As + k*32 + tr*8;
            float4 a0 = *(const float4*)Ak;
            float4 a1 = *(const float4*)(Ak + 4);
            const float* Bk = Bs + k*512;
            unsigned long long b0 = *(const unsigned long long*)(Bk + jj);
            unsigned long long b1 = *(const unsigned long long*)(Bk + 128 + jj);
            unsigned long long b2 = *(const unsigned long long*)(Bk + 256 + jj);
            unsigned long long b3 = *(const unsigned long long*)(Bk + 384 + jj);
            float av[8] = {a0.x,a0.y,a0.z,a0.w,a1.x,a1.y,a1.z,a1.w};
#pragma unroll
            for (int i = 0; i < 8; i++){
                unsigned long long ap = pack2(av[i]);
                fma2(acc[i][0], ap, b0);
                fma2(acc[i][1], ap, b1);
                fma2(acc[i][2], ap, b2);
                fma2(acc[i][3], ap, b3);
            }
        }
    }
    float2 bv[4];
#pragma unroll
    for (int q = 0; q < 4; q++) bv[q] = *(const float2*)(bias + q*128 + jj);
#pragma unroll
    for (int i = 0; i < 8; i++){
        size_t r = (size_t)(block_row + tr*8 + i) * 512;
#pragma unroll
        for (int q = 0; q < 4; q++){
            float2 v = up2(acc[i][q]);
            v.x += bv[q].x; v.y += bv[q].y;
            *(float2*)(X + r + q*128 + jj) = v;
        }
    }
}

// ---------------- t=0: hs=cs=0 -> pure gather + pointwise ----------------
__global__ void lstm_first_kernel(const float* __restrict__ X, const int* __restrict__ nbr,
                                  float* __restrict__ hs, float* __restrict__ cs)
{
    int node = blockIdx.x*8 + (threadIdx.x >> 5);
    int lane = threadIdx.x & 31;
    if (node >= NN) return;
    size_t r = (size_t)__ldg(&nbr[node*DD]) * 512;
    size_t o = (size_t)node*HH;
#pragma unroll
    for (int s = 0; s < 4; s++){
        int c = s*32 + lane;
        float I = __ldg(X + r + c);
        float F = __ldg(X + r + 128 + c);   (void)F;
        float G = __ldg(X + r + 256 + c);
        float O = __ldg(X + r + 384 + c);
        float cv = sigf(I) * tanhf(G);
        cs[o + c] = cv;
        hs[o + c] = sigf(O) * tanhf(cv);
    }
}

// ---------------- LSTM step t>=1: gates = Xgather + hs @ Whh^T ----------------
// BM=32, 512 cols, K=128, 256 threads, 2 CTA/SM. X rows prefetched via cp.async into smem.
__global__ void __launch_bounds__(256, 2) lstm_step_kernel(
    const float* __restrict__ X, const int* __restrict__ nbr, int t,
    const float* __restrict__ Bt,   // Whh^T [128][512]
    const float* __restrict__ hs_in, float* __restrict__ hs_out,
    float* __restrict__ cs)
{
    extern __shared__ __align__(16) float smem[];
    float* Xs = smem;                 // [32][512] = 64KB
    float* Bs = smem + 32*512;        // [16][512] = 32KB
    float* As = Bs + 16*512;          // [16][32]

    int tid = threadIdx.x;
    int block_row = blockIdx.x * 32;

    // prefetch X rows (gather via nbr) into smem: 8 threads/row x 256B each
    {
        int m    = tid >> 3;
        int part = tid & 7;
        size_t src = (size_t)__ldg(&nbr[(block_row + m)*DD + t]) * 512 + part*64;
        uint32_t dst = smem_u32(Xs + m*512 + part*64);
        const float* sp = X + src;
#pragma unroll
        for (int q = 0; q < 16; q++) cp_async16(dst + q*16, sp + q*4);
        CP_COMMIT();
    }

    unsigned long long acc[8][4];
#pragma unroll
    for (int i = 0; i < 8; i++){ acc[i][0]=0ull; acc[i][1]=0ull; acc[i][2]=0ull; acc[i][3]=0ull; }

    int tr = tid >> 6;
    int tc = tid & 63;
    int jj = tc * 2;

    for (int k0 = 0; k0 < 128; k0 += 16){
        __syncthreads();
        const float4* Bg = (const float4*)(Bt + k0*512);
        float4* Bs4 = (float4*)Bs;
#pragma unroll
        for (int i = 0; i < 8; i++) Bs4[tid + i*256] = Bg[tid + i*256];
        if (tid < 128){
            int m  = tid >> 2;
            int kq = (tid & 3) * 4;
            float4 v = *(const float4*)(hs_in + (size_t)(block_row + m)*HH + k0 + kq);
            As[(kq+0)*32 + m] = v.x;
            As[(kq+1)*32 + m] = v.y;
            As[(kq+2)*32 + m] = v.z;
            As[(kq+3)*32 + m] = v.w;
        }
        __syncthreads();
#pragma unroll
        for (int k = 0; k < 16; k++){
            const float* Ak = As + k*32 + tr*8;
            float4 a0 = *(const float4*)Ak;
            float4 a1 = *(const float4*)(Ak + 4);
            const float* Bk = Bs + k*512;
            unsigned long long b0 = *(const unsigned long long*)(Bk + jj);
            unsigned long long b1 = *(const unsigned long long*)(Bk + 128 + jj);
            unsigned long long b2 = *(const unsigned long long*)(Bk + 256 + jj);
            unsigned long long b3 = *(const unsigned long long*)(Bk + 384 + jj);
            float av[8] = {a0.x,a0.y,a0.z,a0.w,a1.x,a1.y,a1.z,a1.w};
#pragma unroll
            for (int i = 0; i < 8; i++){
                unsigned long long ap = pack2(av[i]);
                fma2(acc[i][0], ap, b0);
                fma2(acc[i][1], ap, b1);
                fma2(acc[i][2], ap, b2);
                fma2(acc[i][3], ap, b3);
            }
        }
    }
    CP_WAIT0();
    __syncthreads();

    // fused LSTM pointwise
#pragma unroll
    for (int i = 0; i < 8; i++){
        int m   = tr*8 + i;
        int row = block_row + m;
        size_t off = (size_t)row*HH + jj;
        const float* Xr = Xs + m*512;
        float2 I = up2(acc[i][0]);
        float2 F = up2(acc[i][1]);
        float2 G = up2(acc[i][2]);
        float2 O = up2(acc[i][3]);
        float2 xi = *(const float2*)(Xr + jj);
        float2 xf = *(const float2*)(Xr + 128 + jj);
        float2 xg = *(const float2*)(Xr + 256 + jj);
        float2 xo = *(const float2*)(Xr + 384 + jj);
        I.x += xi.x; I.y += xi.y;
        F.x += xf.x; F.y += xf.y;
        G.x += xg.x; G.y += xg.y;
        O.x += xo.x; O.y += xo.y;
        float2 cold = *(const float2*)(cs + off);
        float cx = sigf(F.x)*cold.x + sigf(I.x)*tanhf(G.x);
        float cy = sigf(F.y)*cold.y + sigf(I.y)*tanhf(G.y);
        float hx = sigf(O.x) * tanhf(cx);
        float hy = sigf(O.y) * tanhf(cy);
        *(float2*)(cs + off)     = make_float2(cx, cy);
        *(float2*)(hs_out + off) = make_float2(hx, hy);
    }
}

// ---------------- fp32 GEMM [N,Ktot] @ Bt[Ktot][128] + bias (+relu) ----------------
__global__ void __launch_bounds__(256) gemm_bias_act_kernel(
    const float* __restrict__ A0, const float* __restrict__ A1,
    const float* __restrict__ Bt, const float* __restrict__ bias,
    float* __restrict__ Cout, int Ktot, int doRelu)
{
    __shared__ __align__(16) float Bs[16*128];
    __shared__ __align__(16) float As[16*64];
    int tid = threadIdx.x;
    int block_row = blockIdx.x * 64;
    int tr = tid >> 5;
    int tc = tid & 31;
    float acc[8][4];
#pragma unroll
    for (int i = 0; i < 8; i++){ acc[i][0]=0.f; acc[i][1]=0.f; acc[i][2]=0.f; acc[i][3]=0.f; }

    for (int k0 = 0; k0 < Ktot; k0 += 16){
        __syncthreads();
        const float4* Bg = (const float4*)(Bt + k0*128);
        float4* Bs4 = (float4*)Bs;
        Bs4[tid]       = Bg[tid];
        Bs4[tid + 256] = Bg[tid + 256];
        {
            int m  = tid >> 2;
            int kq = (tid & 3) * 4;
            int krow = k0 + kq;
            int row = block_row + m;
            float4 v = make_float4(0.f, 0.f, 0.f, 0.f);
            if (row < NN){
                const float* src = (krow < 128) ? (A0 + (size_t)row*HH + krow)
                                                : (A1 + (size_t)row*HH + (krow - 128));
                v = *(const float4*)src;
            }
            As[(kq+0)*64 + m] = v.x;
            As[(kq+1)*64 + m] = v.y;
            As[(kq+2)*64 + m] = v.z;
            As[(kq+3)*64 + m] = v.w;
        }
        __syncthreads();
#pragma unroll
        for (int k = 0; k < 16; k++){
            const float* Ak = As + k*64 + tr*8;
            float4 a0 = *(const float4*)Ak;
            float4 a1 = *(const float4*)(Ak + 4);
            float4 bv = *(const float4*)(Bs + k*128 + tc*4);
            float av[8] = {a0.x,a0.y,a0.z,a0.w,a1.x,a1.y,a1.z,a1.w};
            float bw[4] = {bv.x,bv.y,bv.z,bv.w};
#pragma unroll
            for (int i = 0; i < 8; i++)
#pragma unroll
                for (int j = 0; j < 4; j++)
                    acc[i][j] = fmaf(av[i], bw[j], acc[i][j]);
        }
    }
    float4 bb = *(const float4*)(bias + tc*4);
    float bbv[4] = {bb.x, bb.y, bb.z, bb.w};
#pragma unroll
    for (int i = 0; i < 8; i++){
        int row = block_row + tr*8 + i;
        if (row < NN){
            float4 o;
            float v0 = acc[i][0] + bbv[0];
            float v1 = acc[i][1] + bbv[1];
            float v2 = acc[i][2] + bbv[2];
            float v3 = acc[i][3] + bbv[3];
            if (doRelu){ v0=fmaxf(v0,0.f); v1=fmaxf(v1,0.f); v2=fmaxf(v2,0.f); v3=fmaxf(v3,0.f); }
            o.x=v0; o.y=v1; o.z=v2; o.w=v3;
            *(float4*)(Cout + (size_t)row*HH + tc*4) = o;
        }
    }
}

// ---------------- small output heads ----------------
__global__ void head_out_kernel(const float* __restrict__ x, const float* __restrict__ W,
                                const float* __restrict__ b, float* __restrict__ out, int Cn)
{
    int gwarp = (blockIdx.x * blockDim.x + threadIdx.x) >> 5;
    int lane  = threadIdx.x & 31;
    if (gwarp >= NN) return;
    const float* xr = x + (size_t)gwarp*HH;
    float x0 = xr[lane], x1 = xr[32+lane], x2 = xr[64+lane], x3 = xr[96+lane];
    for (int c = 0; c < Cn; c++){
        const float* w = W + c*HH;
        float s = x0*w[lane] + x1*w[32+lane] + x2*w[64+lane] + x3*w[96+lane];
        s += __shfl_xor_sync(0xffffffffu, s, 16);
        s += __shfl_xor_sync(0xffffffffu, s, 8);
        s += __shfl_xor_sync(0xffffffffu, s, 4);
        s += __shfl_xor_sync(0xffffffffu, s, 2);
        s += __shfl_xor_sync(0xffffffffu, s, 1);
        if (lane == 0) out[(size_t)gwarp*Cn + c] = s + b[c];
    }
}

// ---------------- launch ----------------
extern "C" void kernel_launch(void* const* d_in, const int* in_sizes, int n_in,
                              void* d_out, int out_size)
{
    const float* h_in   = (const float*)d_in[0];
    const int*   nbr    = (const int*)  d_in[1];
    const float* Wih    = (const float*)d_in[2];
    const float* Whh    = (const float*)d_in[3];
    const float* lstmb  = (const float*)d_in[4];
    const float* Wself  = (const float*)d_in[5];
    const float* bself  = (const float*)d_in[6];
    const float* Wneigh = (const float*)d_in[7];
    const float* bneigh = (const float*)d_in[8];
    const float* clsW   = (const float*)d_in[9];
    const float* clsb   = (const float*)d_in[10];
    const float* clsoW  = (const float*)d_in[11];
    const float* clsob  = (const float*)d_in[12];
    const float* cnfW   = (const float*)d_in[13];
    const float* cnfb   = (const float*)d_in[14];
    const float* cnfoW  = (const float*)d_in[15];
    const float* cnfob  = (const float*)d_in[16];

    float *p_X, *p_h, *p_hs, *p_hs2, *p_cs, *p_BtX, *p_BtH, *p_BtS, *p_bS, *p_BtM;
    cudaGetSymbolAddress((void**)&p_X,   g_X);
    cudaGetSymbolAddress((void**)&p_h,   g_h);
    cudaGetSymbolAddress((void**)&p_hs,  g_hs);
    cudaGetSymbolAddress((void**)&p_hs2, g_hs2);
    cudaGetSymbolAddress((void**)&p_cs,  g_cs);
    cudaGetSymbolAddress((void**)&p_BtX, g_BtX);
    cudaGetSymbolAddress((void**)&p_BtH, g_BtH);
    cudaGetSymbolAddress((void**)&p_BtS, g_BtS);
    cudaGetSymbolAddress((void**)&p_bS,  g_bS);
    cudaGetSymbolAddress((void**)&p_BtM, g_BtM);

    float* out   = (float*)d_out;
    float* o_out = out;
    float* h_out = out + (size_t)NN*CC;
    float* l_out = out + (size_t)NN*CC + (size_t)NN*HH;

    const int SMEM_STEP = (32*512 + 16*512 + 16*32) * 4;   // Xs + Bs + As = ~98.3KB
    cudaFuncSetAttribute(lstm_step_kernel, cudaFuncAttributeMaxDynamicSharedMemorySize, SMEM_STEP);

    const int xgrid = NN/32;           // 3125 (NN % 32 == 0)
    const int gemm_grid = (NN + 63)/64;

    // #1: lstm weight transposes
    prep_lstm_t<<<(LL*128*512 + 255)/256, 256>>>(Wih, Whh, p_BtX, p_BtH);

    const float* hcur = h_in;
    for (int layer = 0; layer < LL; layer++){
        // precompute X = hcur @ Wih^T + b   (layer 0: our launch #2)
        precompute_x_kernel<<<xgrid, 256>>>(hcur, p_BtX + layer*128*512, lstmb + layer*512, p_X);
        // t=0 (launch #3)
        lstm_first_kernel<<<NN/8, 256>>>(p_X, nbr, p_hs, p_cs);
        // t=1..15  (layer-0 t=1 is our launch #4 -> ncu capture target)
        for (int t = 1; t < DD; t++){
            float* hs_o = (t & 1) ? p_hs2 : p_hs;
            const float* hs_i = (t & 1) ? p_hs : p_hs2;
            lstm_step_kernel<<<xgrid, 256, SMEM_STEP>>>(p_X, nbr, t,
                p_BtH + layer*128*512, hs_i, hs_o, p_cs);
        }
        if (layer == 0){
            // remaining preps (needed only from here on)
            prep_sage_kernel<<<(LL*256*128 + 255)/256, 256>>>(Wself, Wneigh, p_BtS);
            prep_bias_kernel<<<1, 256>>>(bself, bneigh, p_bS);
            prep_mlp_kernel<<<(10*128*128 + 255)/256, 256>>>(clsW, cnfW, p_BtM);
        }
        // sage combine: relu(h@Ws^T + hs_final@Wn^T + b); final step t=15 wrote p_hs2
        float* dst = (layer == 0) ? p_h : h_out;
        gemm_bias_act_kernel<<<gemm_grid, 256>>>(hcur, p_hs2,
            p_BtS + layer*256*128, p_bS + layer*128, dst, 256, 1);
        hcur = dst;
    }

    // classification head
    gemm_bias_act_kernel<<<gemm_grid, 256>>>(h_out, nullptr, p_BtM + 0*16384, clsb + 0*128, p_hs, 128, 1);
    gemm_bias_act_kernel<<<gemm_grid, 256>>>(p_hs,  nullptr, p_BtM + 1*16384, clsb + 1*128, p_cs, 128, 1);
    gemm_bias_act_kernel<<<gemm_grid, 256>>>(p_cs,  nullptr, p_BtM + 2*16384, clsb + 2*128, p_hs, 128, 1);
    gemm_bias_act_kernel<<<gemm_grid, 256>>>(p_hs,  nullptr, p_BtM + 3*16384, clsb + 3*128, p_cs, 128, 1);
    gemm_bias_act_kernel<<<gemm_grid, 256>>>(p_cs,  nullptr, p_BtM + 4*16384, clsb + 4*128, p_hs, 128, 1);
    head_out_kernel<<<(NN*32 + 255)/256, 256>>>(p_hs, clsoW, clsob, o_out, CC);

    // confidence head
    gemm_bias_act_kernel<<<gemm_grid, 256>>>(h_out, nullptr, p_BtM + 5*16384, cnfb + 0*128, p_hs, 128, 1);
    gemm_bias_act_kernel<<<gemm_grid, 256>>>(p_hs,  nullptr, p_BtM + 6*16384, cnfb + 1*128, p_cs, 128, 1);
    gemm_bias_act_kernel<<<gemm_grid, 256>>>(p_cs,  nullptr, p_BtM + 7*16384, cnfb + 2*128, p_hs, 128, 1);
    gemm_bias_act_kernel<<<gemm_grid, 256>>>(p_hs,  nullptr, p_BtM + 8*16384, cnfb + 3*128, p_cs, 128, 1);
    gemm_bias_act_kernel<<<gemm_grid, 256>>>(p_cs,  nullptr, p_BtM + 9*16384, cnfb + 4*128, p_hs, 128, 1);
    head_out_kernel<<<(NN*32 + 255)/256, 256>>>(p_hs, cnfoW, cnfob, l_out, 1);
}

// round 5
// speedup vs baseline: 1.6614x; 1.0087x over previous
#include <cuda_runtime.h>
#include <cstdint>

#define NN 100000
#define DD 16
#define HH 128
#define LL 2
#define CC 10
#define PITCH 36

// ---------------- device scratch ----------------
__device__ float g_X  [(size_t)NN*512];   // gate-interleaved X: [node][pair p][gate g][e]  (idx = p*8+g*2+e)
__device__ float g_h  [NN*HH];            // layer-0 sage output
__device__ float g_hs [NN*HH];            // lstm final hs / MLP pong
__device__ float g_cs [NN*HH];            // MLP ping
__device__ float g_BtX[LL*128*512];       // Wih^T  [l][k][n]
__device__ float g_BtH[LL*128*512];       // Whh^T  [l][k][n]
__device__ float g_BtS[LL*256*128];       // sage   [l][k][j]
__device__ float g_bS [LL*128];
__device__ float g_BtM[10*128*128];

// ---------------- helpers ----------------
__device__ __forceinline__ unsigned long long pack2(float x){
    unsigned long long r; unsigned u = __float_as_uint(x);
    asm("mov.b64 %0, {%1, %1};" : "=l"(r) : "r"(u));
    return r;
}
__device__ __forceinline__ void fma2(unsigned long long &d, unsigned long long a, unsigned long long b){
    asm("fma.rn.f32x2 %0, %1, %2, %0;" : "+l"(d) : "l"(a), "l"(b));
}
__device__ __forceinline__ float2 up2(unsigned long long v){
    return make_float2(__uint_as_float((unsigned)v), __uint_as_float((unsigned)(v >> 32)));
}
__device__ __forceinline__ float sigf(float x){ return 1.f/(1.f + __expf(-x)); }
__device__ __forceinline__ uint32_t smem_u32(const void* p){
    uint32_t a;
    asm("{ .reg .u64 t; cvta.to.shared.u64 t, %1; cvt.u32.u64 %0, t; }" : "=r"(a) : "l"(p));
    return a;
}
__device__ __forceinline__ void cp_async16(uint32_t dst, const void* src){
    asm volatile("cp.async.cg.shared.global [%0], [%1], 16;" :: "r"(dst), "l"(src));
}
#define CP_COMMIT() asm volatile("cp.async.commit_group;" ::: "memory")
#define CP_WAIT1()  asm volatile("cp.async.wait_group 1;" ::: "memory")
#define CP_WAIT0()  asm volatile("cp.async.wait_group 0;" ::: "memory")

// ---------------- prep: weight transposes ----------------
__global__ void prep_lstm_t(const float* __restrict__ Wih, const float* __restrict__ Whh,
                            float* __restrict__ BtX, float* __restrict__ BtH){
    int idx = blockIdx.x*blockDim.x + threadIdx.x;
    if (idx >= LL*128*512) return;
    int n = idx & 511;
    int k = (idx >> 9) & 127;
    int l = idx >> 16;
    BtX[idx] = Wih[(l*512 + n)*128 + k];
    BtH[idx] = Whh[(l*512 + n)*128 + k];
}
__global__ void prep_sage_kernel(const float* __restrict__ Ws, const float* __restrict__ Wn,
                                 float* __restrict__ Bt){
    int idx = blockIdx.x*blockDim.x + threadIdx.x;
    if (idx >= LL*256*128) return;
    int j = idx & 127;
    int k = (idx >> 7) & 255;
    int l = idx >> 15;
    Bt[idx] = (k < 128) ? Ws[(l*128 + j)*128 + k] : Wn[(l*128 + j)*128 + (k-128)];
}
__global__ void prep_bias_kernel(const float* __restrict__ bs, const float* __restrict__ bn,
                                 float* __restrict__ bS){
    int idx = threadIdx.x;
    if (idx < LL*128) bS[idx] = bs[idx] + bn[idx];
}
__global__ void prep_mlp_kernel(const float* __restrict__ clsW, const float* __restrict__ cnfW,
                                float* __restrict__ Bt){
    int idx = blockIdx.x*blockDim.x + threadIdx.x;
    if (idx >= 10*128*128) return;
    int j = idx & 127;
    int k = (idx >> 7) & 127;
    int hd = idx >> 14;
    const float* W = (hd < 5) ? (clsW + hd*16384) : (cnfW + (hd-5)*16384);
    Bt[idx] = W[j*128 + k];
}

// ---------------- precompute X = h @ Wih^T + b, stored gate-interleaved ----------------
__global__ void __launch_bounds__(256, 2) precompute_x_kernel(
    const float* __restrict__ hsrc, const float* __restrict__ Bt,  // [128][512]
    const float* __restrict__ bias, float* __restrict__ X)
{
    __shared__ __align__(16) float Bs[16*512];
    __shared__ __align__(16) float As[16*32];
    int tid = threadIdx.x;
    int block_row = blockIdx.x * 32;

    unsigned long long acc[8][4];
#pragma unroll
    for (int i = 0; i < 8; i++){ acc[i][0]=0ull; acc[i][1]=0ull; acc[i][2]=0ull; acc[i][3]=0ull; }

    int tr = tid >> 6;
    int tc = tid & 63;
    int jj = tc * 2;

    for (int k0 = 0; k0 < 128; k0 += 16){
        __syncthreads();
        const float4* Bg = (const float4*)(Bt + k0*512);
        float4* Bs4 = (float4*)Bs;
#pragma unroll
        for (int i = 0; i < 8; i++) Bs4[tid + i*256] = Bg[tid + i*256];
        if (tid < 128){
            int m  = tid >> 2;
            int kq = (tid & 3) * 4;
            float4 v = *(const float4*)(hsrc + (size_t)(block_row + m)*HH + k0 + kq);
            As[(kq+0)*32 + m] = v.x;
            As[(kq+1)*32 + m] = v.y;
            As[(kq+2)*32 + m] = v.z;
            As[(kq+3)*32 + m] = v.w;
        }
        __syncthreads();
#pragma unroll
        for (int k = 0; k < 16; k++){
            const float* Ak = As + k*32 + tr*8;
            float4 a0 = *(const float4*)Ak;
            float4 a1 = *(const float4*)(Ak + 4);
            const float* Bk = Bs + k*512;
            unsigned long long b0 = *(const unsigned long long*)(Bk + jj);
            unsigned long long b1 = *(const unsigned long long*)(Bk + 128 + jj);
            unsigned long long b2 = *(const unsigned long long*)(Bk + 256 + jj);
            unsigned long long b3 = *(const unsigned long long*)(Bk + 384 + jj);
            float av[8] = {a0.x,a0.y,a0.z,a0.w,a1.x,a1.y,a1.z,a1.w};
#pragma unroll
            for (int i = 0; i < 8; i++){
                unsigned long long ap = pack2(av[i]);
                fma2(acc[i][0], ap, b0);
                fma2(acc[i][1], ap, b1);
                fma2(acc[i][2], ap, b2);
                fma2(acc[i][3], ap, b3);
            }
        }
    }
    float2 bv[4];
#pragma unroll
    for (int q = 0; q < 4; q++) bv[q] = *(const float2*)(bias + q*128 + jj);
#pragma unroll
    for (int i = 0; i < 8; i++){
        size_t r = (size_t)(block_row + tr*8 + i) * 512;
#pragma unroll
        for (int q = 0; q < 4; q++){
            float2 v = up2(acc[i][q]);
            v.x += bv[q].x; v.y += bv[q].y;
            // interleaved: [pair tc][gate q][e]
            *(float2*)(X + r + (size_t)tc*8 + q*2) = v;
        }
    }
}

// ---------------- persistent per-layer LSTM kernel ----------------
// One CTA owns 32 nodes for all 16 timesteps. hs kept transposed in smem (AsT),
// cs in smem, X gathered directly from the interleaved global image.
// smem: Bs[2][8][512] (32KB, cp.async double buffer) | AsT[128][36] (18KB) | cs_s[32][128] (16KB)
#define SMEM_L ((2*8*512 + 128*PITCH + 32*128) * 4)

__global__ void __launch_bounds__(256, 2) lstm_layer_kernel(
    const float* __restrict__ Xi, const int* __restrict__ nbr,
    const float* __restrict__ Bt,    // Whh^T [128][512]
    float* __restrict__ hsF)         // [N][128] final hidden state
{
    extern __shared__ __align__(16) float smem[];
    float* Bs   = smem;                       // 8192 floats
    float* AsT  = smem + 8192;                // [k][m] pitch 36
    float* cs_s = AsT + 128*PITCH;            // [m][128]

    const int tid = threadIdx.x;
    const int tr = tid >> 6, tc = tid & 63, jj = tc*2;
    const int base = blockIdx.x * 32;
    const uint32_t sb_Bs = smem_u32(smem);

    // ---- t = 0 : hs=cs=0, epilogue only ----
#pragma unroll
    for (int i = 0; i < 8; i++){
        int m = tr*8 + i;
        int node = base + m;
        const float* xp = Xi + (size_t)__ldg(&nbr[node*DD]) * 512 + tc*8;
        float4 v0 = __ldg((const float4*)xp);
        float4 v1 = __ldg((const float4*)xp + 1);
        // v0 = (I0,I1,F0,F1), v1 = (G0,G1,O0,O1)
        float c0 = sigf(v0.x) * tanhf(v1.x);
        float c1 = sigf(v0.y) * tanhf(v1.y);
        cs_s[m*128 + jj]     = c0;
        cs_s[m*128 + jj + 1] = c1;
        AsT[jj*PITCH + m]       = sigf(v1.z) * tanhf(c0);
        AsT[(jj+1)*PITCH + m]   = sigf(v1.w) * tanhf(c1);
    }
    __syncthreads();

    // ---- t = 1..15 ----
    for (int t = 1; t < DD; t++){
        unsigned long long acc[8][4];
#pragma unroll
        for (int i = 0; i < 8; i++){ acc[i][0]=0ull; acc[i][1]=0ull; acc[i][2]=0ull; acc[i][3]=0ull; }

        // prefetch B tile 0
        {
            const float* src = Bt + tid*16;
            uint32_t dst = sb_Bs + tid*64;
#pragma unroll
            for (int q = 0; q < 4; q++) cp_async16(dst + q*16, src + q*4);
            CP_COMMIT();
        }
        for (int tile = 0; tile < 16; tile++){
            if (tile < 15){
                const float* src = Bt + (tile+1)*4096 + tid*16;
                uint32_t dst = sb_Bs + (uint32_t)(((tile+1)&1)*16384) + tid*64;
#pragma unroll
                for (int q = 0; q < 4; q++) cp_async16(dst + q*16, src + q*4);
                CP_COMMIT();
                CP_WAIT1();
            } else {
                CP_WAIT0();
            }
            __syncthreads();
            const float* Bsb = Bs + (tile & 1) * 4096;
#pragma unroll
            for (int kk = 0; kk < 8; kk++){
                int k = tile*8 + kk;
                const float* Ak = AsT + k*PITCH + tr*8;
                float4 a0 = *(const float4*)Ak;
                float4 a1 = *(const float4*)(Ak + 4);
                const float* Bk = Bsb + kk*512;
                unsigned long long b0 = *(const unsigned long long*)(Bk + jj);
                unsigned long long b1 = *(const unsigned long long*)(Bk + 128 + jj);
                unsigned long long b2 = *(const unsigned long long*)(Bk + 256 + jj);
                unsigned long long b3 = *(const unsigned long long*)(Bk + 384 + jj);
                float av[8] = {a0.x,a0.y,a0.z,a0.w,a1.x,a1.y,a1.z,a1.w};
#pragma unroll
                for (int i = 0; i < 8; i++){
                    unsigned long long ap = pack2(av[i]);
                    fma2(acc[i][0], ap, b0);
                    fma2(acc[i][1], ap, b1);
                    fma2(acc[i][2], ap, b2);
                    fma2(acc[i][3], ap, b3);
                }
            }
            __syncthreads();   // Bs buffer free before it is overwritten
        }

        // ---- fused LSTM epilogue ----
#pragma unroll
        for (int i = 0; i < 8; i++){
            int m = tr*8 + i;
            int node = base + m;
            const float* xp = Xi + (size_t)__ldg(&nbr[node*DD + t]) * 512 + tc*8;
            float4 v0 = __ldg((const float4*)xp);
            float4 v1 = __ldg((const float4*)xp + 1);
            float2 I = up2(acc[i][0]);
            float2 F = up2(acc[i][1]);
            float2 G = up2(acc[i][2]);
            float2 O = up2(acc[i][3]);
            I.x += v0.x; I.y += v0.y;
            F.x += v0.z; F.y += v0.w;
            G.x += v1.x; G.y += v1.y;
            O.x += v1.z; O.y += v1.w;
            float2 cold = *(const float2*)(cs_s + m*128 + jj);
            float c0 = sigf(F.x)*cold.x + sigf(I.x)*tanhf(G.x);
            float c1 = sigf(F.y)*cold.y + sigf(I.y)*tanhf(G.y);
            float h0 = sigf(O.x) * tanhf(c0);
            float h1 = sigf(O.y) * tanhf(c1);
            *(float2*)(cs_s + m*128 + jj) = make_float2(c0, c1);
            AsT[jj*PITCH + m]     = h0;
            AsT[(jj+1)*PITCH + m] = h1;
            if (t == DD-1)
                *(float2*)(hsF + (size_t)node*HH + jj) = make_float2(h0, h1);
        }
        __syncthreads();
    }
}

// ---------------- fp32 f32x2 GEMM [N,Ktot] @ Bt[Ktot][128] + bias (+relu) ----------------
__global__ void __launch_bounds__(256) gemm_bias_act_kernel(
    const float* __restrict__ A0, const float* __restrict__ A1,
    const float* __restrict__ Bt, const float* __restrict__ bias,
    float* __restrict__ Cout, int Ktot, int doRelu)
{
    __shared__ __align__(16) float Bs[16*128];
    __shared__ __align__(16) float As[16*64];
    int tid = threadIdx.x;
    int block_row = blockIdx.x * 64;
    int tr = tid >> 5;
    int tc = tid & 31;
    int jj4 = tc * 4;
    unsigned long long acc[8][2];
#pragma unroll
    for (int i = 0; i < 8; i++){ acc[i][0]=0ull; acc[i][1]=0ull; }

    for (int k0 = 0; k0 < Ktot; k0 += 16){
        __syncthreads();
        const float4* Bg = (const float4*)(Bt + k0*128);
        float4* Bs4 = (float4*)Bs;
        Bs4[tid]       = Bg[tid];
        Bs4[tid + 256] = Bg[tid + 256];
        {
            int m  = tid >> 2;
            int kq = (tid & 3) * 4;
            int krow = k0 + kq;
            int row = block_row + m;
            float4 v = make_float4(0.f, 0.f, 0.f, 0.f);
            if (row < NN){
                const float* src = (krow < 128) ? (A0 + (size_t)row*HH + krow)
                                                : (A1 + (size_t)row*HH + (krow - 128));
                v = *(const float4*)src;
            }
            As[(kq+0)*64 + m] = v.x;
            As[(kq+1)*64 + m] = v.y;
            As[(kq+2)*64 + m] = v.z;
            As[(kq+3)*64 + m] = v.w;
        }
        __syncthreads();
#pragma unroll
        for (int k = 0; k < 16; k++){
            const float* Ak = As + k*64 + tr*8;
            float4 a0 = *(const float4*)Ak;
            float4 a1 = *(const float4*)(Ak + 4);
            unsigned long long b0 = *(const unsigned long long*)(Bs + k*128 + jj4);
            unsigned long long b1 = *(const unsigned long long*)(Bs + k*128 + jj4 + 2);
            float av[8] = {a0.x,a0.y,a0.z,a0.w,a1.x,a1.y,a1.z,a1.w};
#pragma unroll
            for (int i = 0; i < 8; i++){
                unsigned long long ap = pack2(av[i]);
                fma2(acc[i][0], ap, b0);
                fma2(acc[i][1], ap, b1);
            }
        }
    }
    float2 bb0 = *(const float2*)(bias + jj4);
    float2 bb1 = *(const float2*)(bias + jj4 + 2);
#pragma unroll
    for (int i = 0; i < 8; i++){
        int row = block_row + tr*8 + i;
        if (row < NN){
            float2 v0 = up2(acc[i][0]);
            float2 v1 = up2(acc[i][1]);
            v0.x += bb0.x; v0.y += bb0.y;
            v1.x += bb1.x; v1.y += bb1.y;
            if (doRelu){
                v0.x = fmaxf(v0.x, 0.f); v0.y = fmaxf(v0.y, 0.f);
                v1.x = fmaxf(v1.x, 0.f); v1.y = fmaxf(v1.y, 0.f);
            }
            float4 o; o.x=v0.x; o.y=v0.y; o.z=v1.x; o.w=v1.y;
            *(float4*)(Cout + (size_t)row*HH + jj4) = o;
        }
    }
}

// ---------------- small output heads ----------------
__global__ void head_out_kernel(const float* __restrict__ x, const float* __restrict__ W,
                                const float* __restrict__ b, float* __restrict__ out, int Cn)
{
    int gwarp = (blockIdx.x * blockDim.x + threadIdx.x) >> 5;
    int lane  = threadIdx.x & 31;
    if (gwarp >= NN) return;
    const float* xr = x + (size_t)gwarp*HH;
    float x0 = xr[lane], x1 = xr[32+lane], x2 = xr[64+lane], x3 = xr[96+lane];
    for (int c = 0; c < Cn; c++){
        const float* w = W + c*HH;
        float s = x0*w[lane] + x1*w[32+lane] + x2*w[64+lane] + x3*w[96+lane];
        s += __shfl_xor_sync(0xffffffffu, s, 16);
        s += __shfl_xor_sync(0xffffffffu, s, 8);
        s += __shfl_xor_sync(0xffffffffu, s, 4);
        s += __shfl_xor_sync(0xffffffffu, s, 2);
        s += __shfl_xor_sync(0xffffffffu, s, 1);
        if (lane == 0) out[(size_t)gwarp*Cn + c] = s + b[c];
    }
}

// ---------------- launch ----------------
extern "C" void kernel_launch(void* const* d_in, const int* in_sizes, int n_in,
                              void* d_out, int out_size)
{
    const float* h_in   = (const float*)d_in[0];
    const int*   nbr    = (const int*)  d_in[1];
    const float* Wih    = (const float*)d_in[2];
    const float* Whh    = (const float*)d_in[3];
    const float* lstmb  = (const float*)d_in[4];
    const float* Wself  = (const float*)d_in[5];
    const float* bself  = (const float*)d_in[6];
    const float* Wneigh = (const float*)d_in[7];
    const float* bneigh = (const float*)d_in[8];
    const float* clsW   = (const float*)d_in[9];
    const float* clsb   = (const float*)d_in[10];
    const float* clsoW  = (const float*)d_in[11];
    const float* clsob  = (const float*)d_in[12];
    const float* cnfW   = (const float*)d_in[13];
    const float* cnfb   = (const float*)d_in[14];
    const float* cnfoW  = (const float*)d_in[15];
    const float* cnfob  = (const float*)d_in[16];

    float *p_X, *p_h, *p_hs, *p_cs, *p_BtX, *p_BtH, *p_BtS, *p_bS, *p_BtM;
    cudaGetSymbolAddress((void**)&p_X,   g_X);
    cudaGetSymbolAddress((void**)&p_h,   g_h);
    cudaGetSymbolAddress((void**)&p_hs,  g_hs);
    cudaGetSymbolAddress((void**)&p_cs,  g_cs);
    cudaGetSymbolAddress((void**)&p_BtX, g_BtX);
    cudaGetSymbolAddress((void**)&p_BtH, g_BtH);
    cudaGetSymbolAddress((void**)&p_BtS, g_BtS);
    cudaGetSymbolAddress((void**)&p_bS,  g_bS);
    cudaGetSymbolAddress((void**)&p_BtM, g_BtM);

    float* out   = (float*)d_out;
    float* o_out = out;
    float* h_out = out + (size_t)NN*CC;
    float* l_out = out + (size_t)NN*CC + (size_t)NN*HH;

    cudaFuncSetAttribute(lstm_layer_kernel, cudaFuncAttributeMaxDynamicSharedMemorySize, SMEM_L);

    const int xgrid = NN/32;           // 3125
    const int gemm_grid = (NN + 63)/64;

    prep_lstm_t<<<(LL*128*512 + 255)/256, 256>>>(Wih, Whh, p_BtX, p_BtH);

    const float* hcur = h_in;
    for (int layer = 0; layer < LL; layer++){
        precompute_x_kernel<<<xgrid, 256>>>(hcur, p_BtX + layer*128*512, lstmb + layer*512, p_X);
        lstm_layer_kernel<<<xgrid, 256, SMEM_L>>>(p_X, nbr, p_BtH + layer*128*512, p_hs);
        if (layer == 0){
            prep_sage_kernel<<<(LL*256*128 + 255)/256, 256>>>(Wself, Wneigh, p_BtS);
            prep_bias_kernel<<<1, 256>>>(bself, bneigh, p_bS);
            prep_mlp_kernel<<<(10*128*128 + 255)/256, 256>>>(clsW, cnfW, p_BtM);
        }
        float* dst = (layer == 0) ? p_h : h_out;
        gemm_bias_act_kernel<<<gemm_grid, 256>>>(hcur, p_hs,
            p_BtS + layer*256*128, p_bS + layer*128, dst, 256, 1);
        hcur = dst;
    }

    // classification head
    gemm_bias_act_kernel<<<gemm_grid, 256>>>(h_out, nullptr, p_BtM + 0*16384, clsb + 0*128, p_cs, 128, 1);
    gemm_bias_act_kernel<<<gemm_grid, 256>>>(p_cs,  nullptr, p_BtM + 1*16384, clsb + 1*128, p_hs, 128, 1);
    gemm_bias_act_kernel<<<gemm_grid, 256>>>(p_hs,  nullptr, p_BtM + 2*16384, clsb + 2*128, p_cs, 128, 1);
    gemm_bias_act_kernel<<<gemm_grid, 256>>>(p_cs,  nullptr, p_BtM + 3*16384, clsb + 3*128, p_hs, 128, 1);
    gemm_bias_act_kernel<<<gemm_grid, 256>>>(p_hs,  nullptr, p_BtM + 4*16384, clsb + 4*128, p_cs, 128, 1);
    head_out_kernel<<<(NN*32 + 255)/256, 256>>>(p_cs, clsoW, clsob, o_out, CC);

    // confidence head
    gemm_bias_act_kernel<<<gemm_grid, 256>>>(h_out, nullptr, p_BtM + 5*16384, cnfb + 0*128, p_hs, 128, 1);
    gemm_bias_act_kernel<<<gemm_grid, 256>>>(p_hs,  nullptr, p_BtM + 6*16384, cnfb + 1*128, p_cs, 128, 1);
    gemm_bias_act_kernel<<<gemm_grid, 256>>>(p_cs,  nullptr, p_BtM + 7*16384, cnfb + 2*128, p_hs, 128, 1);
    gemm_bias_act_kernel<<<gemm_grid, 256>>>(p_hs,  nullptr, p_BtM + 8*16384, cnfb + 3*128, p_cs, 128, 1);
    gemm_bias_act_kernel<<<gemm_grid, 256>>>(p_cs,  nullptr, p_BtM + 9*16384, cnfb + 4*128, p_hs, 128, 1);
    head_out_kernel<<<(NN*32 + 255)/256, 256>>>(p_hs, cnfoW, cnfob, l_out, 1);
}

// round 6
// speedup vs baseline: 1.8194x; 1.0951x over previous
#include <cuda_runtime.h>
#include <cstdint>

#define NN 100000
#define DD 16
#define HH 128
#define LL 2
#define CC 10
#define PITCH 36

// ---------------- device scratch ----------------
__device__ float g_X  [(size_t)NN*512];   // gate-interleaved X: [node][pair p][I0 I1 F0 F1 | G0 G1 O0 O1]
__device__ float g_h  [NN*HH];
__device__ float g_hs [NN*HH];
__device__ float g_cs [NN*HH];
__device__ float g_BtX[LL*128*512];       // Wih^T [l][k][n] plain
__device__ float g_BtH[LL*128*512];       // Whh^T [l][k][c] gate-interleaved per k-row
__device__ float g_BtS[LL*256*128];
__device__ float g_bS [LL*128];
__device__ float g_BtM[10*128*128];

// ---------------- helpers ----------------
__device__ __forceinline__ unsigned long long pack2(float x){
    unsigned long long r; unsigned u = __float_as_uint(x);
    asm("mov.b64 %0, {%1, %1};" : "=l"(r) : "r"(u));
    return r;
}
__device__ __forceinline__ void fma2(unsigned long long &d, unsigned long long a, unsigned long long b){
    asm("fma.rn.f32x2 %0, %1, %2, %0;" : "+l"(d) : "l"(a), "l"(b));
}
__device__ __forceinline__ float2 up2(unsigned long long v){
    return make_float2(__uint_as_float((unsigned)v), __uint_as_float((unsigned)(v >> 32)));
}
__device__ __forceinline__ float ex2a(float x){ float r; asm("ex2.approx.f32 %0, %1;" : "=f"(r) : "f"(x)); return r; }
__device__ __forceinline__ float rcpa(float x){ float r; asm("rcp.approx.f32 %0, %1;" : "=f"(r) : "f"(x)); return r; }
#define L2E 1.4426950408889634f
__device__ __forceinline__ float sigf(float x){ return rcpa(1.f + ex2a(-L2E * x)); }
__device__ __forceinline__ float tanhff(float x){ return 1.f - 2.f * rcpa(1.f + ex2a((2.f*L2E) * x)); }
__device__ __forceinline__ uint32_t smem_u32(const void* p){
    uint32_t a;
    asm("{ .reg .u64 t; cvta.to.shared.u64 t, %1; cvt.u32.u64 %0, t; }" : "=r"(a) : "l"(p));
    return a;
}
__device__ __forceinline__ void cp_async16(uint32_t dst, const void* src){
    asm volatile("cp.async.cg.shared.global [%0], [%1], 16;" :: "r"(dst), "l"(src));
}
#define CP_COMMIT() asm volatile("cp.async.commit_group;" ::: "memory")
#define CP_WAIT1()  asm volatile("cp.async.wait_group 1;" ::: "memory")
#define CP_WAIT0()  asm volatile("cp.async.wait_group 0;" ::: "memory")

// ---------------- prep: weight transposes ----------------
// BtX: [l][k][n] plain. BtH: gate-interleaved per k-row:
//   c in [0,256): c = p*4 + g2*2 + e, gate = g2 (0=I,1=F)
//   c in [256,512): gate = 2+g2 (2=G,3=O);  original col n = gate*128 + p*2 + e
__global__ void prep_lstm_t(const float* __restrict__ Wih, const float* __restrict__ Whh,
                            float* __restrict__ BtX, float* __restrict__ BtH){
    int idx = blockIdx.x*blockDim.x + threadIdx.x;
    if (idx >= LL*128*512) return;
    int c = idx & 511;
    int k = (idx >> 9) & 127;
    int l = idx >> 16;
    BtX[idx] = Wih[(l*512 + c)*128 + k];
    int half = c >> 8;
    int r = c & 255;
    int p  = r >> 2;
    int g2 = (r >> 1) & 1;
    int e  = r & 1;
    int n = (half*2 + g2)*128 + p*2 + e;
    BtH[idx] = Whh[(l*512 + n)*128 + k];
}
__global__ void prep_sage_kernel(const float* __restrict__ Ws, const float* __restrict__ Wn,
                                 float* __restrict__ Bt){
    int idx = blockIdx.x*blockDim.x + threadIdx.x;
    if (idx >= LL*256*128) return;
    int j = idx & 127;
    int k = (idx >> 7) & 255;
    int l = idx >> 15;
    Bt[idx] = (k < 128) ? Ws[(l*128 + j)*128 + k] : Wn[(l*128 + j)*128 + (k-128)];
}
__global__ void prep_bias_kernel(const float* __restrict__ bs, const float* __restrict__ bn,
                                 float* __restrict__ bS){
    int idx = threadIdx.x;
    if (idx < LL*128) bS[idx] = bs[idx] + bn[idx];
}
__global__ void prep_mlp_kernel(const float* __restrict__ clsW, const float* __restrict__ cnfW,
                                float* __restrict__ Bt){
    int idx = blockIdx.x*blockDim.x + threadIdx.x;
    if (idx >= 10*128*128) return;
    int j = idx & 127;
    int k = (idx >> 7) & 127;
    int hd = idx >> 14;
    const float* W = (hd < 5) ? (clsW + hd*16384) : (cnfW + (hd-5)*16384);
    Bt[idx] = W[j*128 + k];
}

// ---------------- precompute X = h @ Wih^T + b, stored gate-interleaved ----------------
__global__ void __launch_bounds__(256, 2) precompute_x_kernel(
    const float* __restrict__ hsrc, const float* __restrict__ Bt,
    const float* __restrict__ bias, float* __restrict__ X)
{
    __shared__ __align__(16) float Bs[16*512];
    __shared__ __align__(16) float As[16*32];
    int tid = threadIdx.x;
    int block_row = blockIdx.x * 32;

    unsigned long long acc[8][4];
#pragma unroll
    for (int i = 0; i < 8; i++){ acc[i][0]=0ull; acc[i][1]=0ull; acc[i][2]=0ull; acc[i][3]=0ull; }

    int tr = tid >> 6;
    int tc = tid & 63;
    int jj = tc * 2;

    for (int k0 = 0; k0 < 128; k0 += 16){
        __syncthreads();
        const float4* Bg = (const float4*)(Bt + k0*512);
        float4* Bs4 = (float4*)Bs;
#pragma unroll
        for (int i = 0; i < 8; i++) Bs4[tid + i*256] = Bg[tid + i*256];
        if (tid < 128){
            int m  = tid >> 2;
            int kq = (tid & 3) * 4;
            float4 v = *(const float4*)(hsrc + (size_t)(block_row + m)*HH + k0 + kq);
            As[(kq+0)*32 + m] = v.x;
            As[(kq+1)*32 + m] = v.y;
            As[(kq+2)*32 + m] = v.z;
            As[(kq+3)*32 + m] = v.w;
        }
        __syncthreads();
#pragma unroll
        for (int k = 0; k < 16; k++){
            const float* Ak = As + k*32 + tr*8;
            float4 a0 = *(const float4*)Ak;
            float4 a1 = *(const float4*)(Ak + 4);
            const float* Bk = Bs + k*512;
            unsigned long long b0 = *(const unsigned long long*)(Bk + jj);
            unsigned long long b1 = *(const unsigned long long*)(Bk + 128 + jj);
            unsigned long long b2 = *(const unsigned long long*)(Bk + 256 + jj);
            unsigned long long b3 = *(const unsigned long long*)(Bk + 384 + jj);
            float av[8] = {a0.x,a0.y,a0.z,a0.w,a1.x,a1.y,a1.z,a1.w};
#pragma unroll
            for (int i = 0; i < 8; i++){
                unsigned long long ap = pack2(av[i]);
                fma2(acc[i][0], ap, b0);
                fma2(acc[i][1], ap, b1);
                fma2(acc[i][2], ap, b2);
                fma2(acc[i][3], ap, b3);
            }
        }
    }
    float2 bv[4];
#pragma unroll
    for (int q = 0; q < 4; q++) bv[q] = *(const float2*)(bias + q*128 + jj);
#pragma unroll
    for (int i = 0; i < 8; i++){
        size_t r = (size_t)(block_row + tr*8 + i) * 512;
#pragma unroll
        for (int q = 0; q < 4; q++){
            float2 v = up2(acc[i][q]);
            v.x += bv[q].x; v.y += bv[q].y;
            *(float2*)(X + r + (size_t)tc*8 + q*2) = v;   // [pair tc][I I F F | G G O O]
        }
    }
}

// ---------------- persistent per-layer LSTM kernel ----------------
// smem: Bs[3][8][512] (48KB, cp.async 3-ring) | AsT[128][36] (18KB) | cs_s[32][128] (16KB)
#define SMEM_L ((3*8*512 + 128*PITCH + 32*128) * 4)

__global__ void __launch_bounds__(256, 2) lstm_layer_kernel(
    const float* __restrict__ Xi, const int* __restrict__ nbr,
    const float* __restrict__ Bt,    // Whh^T gate-interleaved [128][512]
    float* __restrict__ hsF)
{
    extern __shared__ __align__(16) float smem[];
    float* Bs   = smem;                       // 3*4096 floats
    float* AsT  = smem + 3*4096;
    float* cs_s = AsT + 128*PITCH;

    const int tid = threadIdx.x;
    const int tr = tid >> 6, tc = tid & 63, jj = tc*2;
    const int base = blockIdx.x * 32;
    const uint32_t sb_Bs = smem_u32(smem);

    // ---- t = 0 : hs=cs=0, epilogue only ----
#pragma unroll
    for (int i = 0; i < 8; i++){
        int m = tr*8 + i;
        int node = base + m;
        const float* xp = Xi + (size_t)__ldg(&nbr[node*DD]) * 512 + tc*8;
        float4 v0 = __ldg((const float4*)xp);
        float4 v1 = __ldg((const float4*)xp + 1);
        float c0 = sigf(v0.x) * tanhff(v1.x);
        float c1 = sigf(v0.y) * tanhff(v1.y);
        cs_s[m*128 + jj]     = c0;
        cs_s[m*128 + jj + 1] = c1;
        AsT[jj*PITCH + m]     = sigf(v1.z) * tanhff(c0);
        AsT[(jj+1)*PITCH + m] = sigf(v1.w) * tanhff(c1);
    }
    __syncthreads();

    // ---- t = 1..15 ----
    for (int t = 1; t < DD; t++){
        unsigned long long acc[8][4];
#pragma unroll
        for (int i = 0; i < 8; i++){ acc[i][0]=0ull; acc[i][1]=0ull; acc[i][2]=0ull; acc[i][3]=0ull; }

        // preamble: prefetch tiles 0,1
#pragma unroll
        for (int pt = 0; pt < 2; pt++){
            const float* src = Bt + pt*4096 + tid*16;
            uint32_t dst = sb_Bs + (uint32_t)(pt*16384) + tid*64;
#pragma unroll
            for (int q = 0; q < 4; q++) cp_async16(dst + q*16, src + q*4);
            CP_COMMIT();
        }

        for (int tile = 0; tile < 16; tile++){
            if (tile == 15) CP_WAIT0(); else CP_WAIT1();
            __syncthreads();
            if (tile < 14){
                int nt = tile + 2;
                const float* src = Bt + nt*4096 + tid*16;
                uint32_t dst = sb_Bs + (uint32_t)((nt % 3)*16384) + tid*64;
#pragma unroll
                for (int q = 0; q < 4; q++) cp_async16(dst + q*16, src + q*4);
                CP_COMMIT();
            }
            const float* Bsb = Bs + (tile % 3) * 4096;
#pragma unroll
            for (int kk = 0; kk < 8; kk++){
                int k = tile*8 + kk;
                const float* Ak = AsT + k*PITCH + tr*8;
                float4 a0 = *(const float4*)Ak;
                float4 a1 = *(const float4*)(Ak + 4);
                const float* Bk = Bsb + kk*512;
                ulonglong2 bIF = *(const ulonglong2*)(Bk + tc*4);
                ulonglong2 bGO = *(const ulonglong2*)(Bk + 256 + tc*4);
                float av[8] = {a0.x,a0.y,a0.z,a0.w,a1.x,a1.y,a1.z,a1.w};
#pragma unroll
                for (int i = 0; i < 8; i++){
                    unsigned long long ap = pack2(av[i]);
                    fma2(acc[i][0], ap, bIF.x);
                    fma2(acc[i][1], ap, bIF.y);
                    fma2(acc[i][2], ap, bGO.x);
                    fma2(acc[i][3], ap, bGO.y);
                }
            }
        }
        __syncthreads();   // all GEMM reads of AsT done before epilogue overwrites it

        // ---- fused LSTM epilogue ----
#pragma unroll
        for (int i = 0; i < 8; i++){
            int m = tr*8 + i;
            int node = base + m;
            const float* xp = Xi + (size_t)__ldg(&nbr[node*DD + t]) * 512 + tc*8;
            float4 v0 = __ldg((const float4*)xp);
            float4 v1 = __ldg((const float4*)xp + 1);
            float2 I = up2(acc[i][0]);
            float2 F = up2(acc[i][1]);
            float2 G = up2(acc[i][2]);
            float2 O = up2(acc[i][3]);
            I.x += v0.x; I.y += v0.y;
            F.x += v0.z; F.y += v0.w;
            G.x += v1.x; G.y += v1.y;
            O.x += v1.z; O.y += v1.w;
            float2 cold = *(const float2*)(cs_s + m*128 + jj);
            float c0 = sigf(F.x)*cold.x + sigf(I.x)*tanhff(G.x);
            float c1 = sigf(F.y)*cold.y + sigf(I.y)*tanhff(G.y);
            float h0 = sigf(O.x) * tanhff(c0);
            float h1 = sigf(O.y) * tanhff(c1);
            *(float2*)(cs_s + m*128 + jj) = make_float2(c0, c1);
            AsT[jj*PITCH + m]     = h0;
            AsT[(jj+1)*PITCH + m] = h1;
            if (t == DD-1)
                *(float2*)(hsF + (size_t)node*HH + jj) = make_float2(h0, h1);
        }
        __syncthreads();
    }
}

// ---------------- fp32 f32x2 GEMM [N,Ktot] @ Bt[Ktot][128] + bias (+relu) ----------------
__global__ void __launch_bounds__(256) gemm_bias_act_kernel(
    const float* __restrict__ A0, const float* __restrict__ A1,
    const float* __restrict__ Bt, const float* __restrict__ bias,
    float* __restrict__ Cout, int Ktot, int doRelu)
{
    __shared__ __align__(16) float Bs[16*128];
    __shared__ __align__(16) float As[16*64];
    int tid = threadIdx.x;
    int block_row = blockIdx.x * 64;
    int tr = tid >> 5;
    int tc = tid & 31;
    int jj4 = tc * 4;
    unsigned long long acc[8][2];
#pragma unroll
    for (int i = 0; i < 8; i++){ acc[i][0]=0ull; acc[i][1]=0ull; }

    for (int k0 = 0; k0 < Ktot; k0 += 16){
        __syncthreads();
        const float4* Bg = (const float4*)(Bt + k0*128);
        float4* Bs4 = (float4*)Bs;
        Bs4[tid]       = Bg[tid];
        Bs4[tid + 256] = Bg[tid + 256];
        {
            int m  = tid >> 2;
            int kq = (tid & 3) * 4;
            int krow = k0 + kq;
            int row = block_row + m;
            float4 v = make_float4(0.f, 0.f, 0.f, 0.f);
            if (row < NN){
                const float* src = (krow < 128) ? (A0 + (size_t)row*HH + krow)
                                                : (A1 + (size_t)row*HH + (krow - 128));
                v = *(const float4*)src;
            }
            As[(kq+0)*64 + m] = v.x;
            As[(kq+1)*64 + m] = v.y;
            As[(kq+2)*64 + m] = v.z;
            As[(kq+3)*64 + m] = v.w;
        }
        __syncthreads();
#pragma unroll
        for (int k = 0; k < 16; k++){
            const float* Ak = As + k*64 + tr*8;
            float4 a0 = *(const float4*)Ak;
            float4 a1 = *(const float4*)(Ak + 4);
            unsigned long long b0 = *(const unsigned long long*)(Bs + k*128 + jj4);
            unsigned long long b1 = *(const unsigned long long*)(Bs + k*128 + jj4 + 2);
            float av[8] = {a0.x,a0.y,a0.z,a0.w,a1.x,a1.y,a1.z,a1.w};
#pragma unroll
            for (int i = 0; i < 8; i++){
                unsigned long long ap = pack2(av[i]);
                fma2(acc[i][0], ap, b0);
                fma2(acc[i][1], ap, b1);
            }
        }
    }
    float2 bb0 = *(const float2*)(bias + jj4);
    float2 bb1 = *(const float2*)(bias + jj4 + 2);
#pragma unroll
    for (int i = 0; i < 8; i++){
        int row = block_row + tr*8 + i;
        if (row < NN){
            float2 v0 = up2(acc[i][0]);
            float2 v1 = up2(acc[i][1]);
            v0.x += bb0.x; v0.y += bb0.y;
            v1.x += bb1.x; v1.y += bb1.y;
            if (doRelu){
                v0.x = fmaxf(v0.x, 0.f); v0.y = fmaxf(v0.y, 0.f);
                v1.x = fmaxf(v1.x, 0.f); v1.y = fmaxf(v1.y, 0.f);
            }
            float4 o; o.x=v0.x; o.y=v0.y; o.z=v1.x; o.w=v1.y;
            *(float4*)(Cout + (size_t)row*HH + jj4) = o;
        }
    }
}

// ---------------- small output heads ----------------
__global__ void head_out_kernel(const float* __restrict__ x, const float* __restrict__ W,
                                const float* __restrict__ b, float* __restrict__ out, int Cn)
{
    int gwarp = (blockIdx.x * blockDim.x + threadIdx.x) >> 5;
    int lane  = threadIdx.x & 31;
    if (gwarp >= NN) return;
    const float* xr = x + (size_t)gwarp*HH;
    float x0 = xr[lane], x1 = xr[32+lane], x2 = xr[64+lane], x3 = xr[96+lane];
    for (int c = 0; c < Cn; c++){
        const float* w = W + c*HH;
        float s = x0*w[lane] + x1*w[32+lane] + x2*w[64+lane] + x3*w[96+lane];
        s += __shfl_xor_sync(0xffffffffu, s, 16);
        s += __shfl_xor_sync(0xffffffffu, s, 8);
        s += __shfl_xor_sync(0xffffffffu, s, 4);
        s += __shfl_xor_sync(0xffffffffu, s, 2);
        s += __shfl_xor_sync(0xffffffffu, s, 1);
        if (lane == 0) out[(size_t)gwarp*Cn + c] = s + b[c];
    }
}

// ---------------- launch ----------------
extern "C" void kernel_launch(void* const* d_in, const int* in_sizes, int n_in,
                              void* d_out, int out_size)
{
    const float* h_in   = (const float*)d_in[0];
    const int*   nbr    = (const int*)  d_in[1];
    const float* Wih    = (const float*)d_in[2];
    const float* Whh    = (const float*)d_in[3];
    const float* lstmb  = (const float*)d_in[4];
    const float* Wself  = (const float*)d_in[5];
    const float* bself  = (const float*)d_in[6];
    const float* Wneigh = (const float*)d_in[7];
    const float* bneigh = (const float*)d_in[8];
    const float* clsW   = (const float*)d_in[9];
    const float* clsb   = (const float*)d_in[10];
    const float* clsoW  = (const float*)d_in[11];
    const float* clsob  = (const float*)d_in[12];
    const float* cnfW   = (const float*)d_in[13];
    const float* cnfb   = (const float*)d_in[14];
    const float* cnfoW  = (const float*)d_in[15];
    const float* cnfob  = (const float*)d_in[16];

    float *p_X, *p_h, *p_hs, *p_cs, *p_BtX, *p_BtH, *p_BtS, *p_bS, *p_BtM;
    cudaGetSymbolAddress((void**)&p_X,   g_X);
    cudaGetSymbolAddress((void**)&p_h,   g_h);
    cudaGetSymbolAddress((void**)&p_hs,  g_hs);
    cudaGetSymbolAddress((void**)&p_cs,  g_cs);
    cudaGetSymbolAddress((void**)&p_BtX, g_BtX);
    cudaGetSymbolAddress((void**)&p_BtH, g_BtH);
    cudaGetSymbolAddress((void**)&p_BtS, g_BtS);
    cudaGetSymbolAddress((void**)&p_bS,  g_bS);
    cudaGetSymbolAddress((void**)&p_BtM, g_BtM);

    float* out   = (float*)d_out;
    float* o_out = out;
    float* h_out = out + (size_t)NN*CC;
    float* l_out = out + (size_t)NN*CC + (size_t)NN*HH;

    cudaFuncSetAttribute(lstm_layer_kernel, cudaFuncAttributeMaxDynamicSharedMemorySize, SMEM_L);

    const int xgrid = NN/32;
    const int gemm_grid = (NN + 63)/64;

    // launches #1-#4: all preps (so launch #6 = lstm_layer_kernel for ncu -s 5 -c 1)
    prep_lstm_t<<<(LL*128*512 + 255)/256, 256>>>(Wih, Whh, p_BtX, p_BtH);
    prep_sage_kernel<<<(LL*256*128 + 255)/256, 256>>>(Wself, Wneigh, p_BtS);
    prep_bias_kernel<<<1, 256>>>(bself, bneigh, p_bS);
    prep_mlp_kernel<<<(10*128*128 + 255)/256, 256>>>(clsW, cnfW, p_BtM);

    const float* hcur = h_in;
    for (int layer = 0; layer < LL; layer++){
        precompute_x_kernel<<<xgrid, 256>>>(hcur, p_BtX + layer*128*512, lstmb + layer*512, p_X);  // #5
        lstm_layer_kernel<<<xgrid, 256, SMEM_L>>>(p_X, nbr, p_BtH + layer*128*512, p_hs);          // #6 <- profiled
        float* dst = (layer == 0) ? p_h : h_out;
        gemm_bias_act_kernel<<<gemm_grid, 256>>>(hcur, p_hs,
            p_BtS + layer*256*128, p_bS + layer*128, dst, 256, 1);
        hcur = dst;
    }

    // classification head
    gemm_bias_act_kernel<<<gemm_grid, 256>>>(h_out, nullptr, p_BtM + 0*16384, clsb + 0*128, p_cs, 128, 1);
    gemm_bias_act_kernel<<<gemm_grid, 256>>>(p_cs,  nullptr, p_BtM + 1*16384, clsb + 1*128, p_hs, 128, 1);
    gemm_bias_act_kernel<<<gemm_grid, 256>>>(p_hs,  nullptr, p_BtM + 2*16384, clsb + 2*128, p_cs, 128, 1);
    gemm_bias_act_kernel<<<gemm_grid, 256>>>(p_cs,  nullptr, p_BtM + 3*16384, clsb + 3*128, p_hs, 128, 1);
    gemm_bias_act_kernel<<<gemm_grid, 256>>>(p_hs,  nullptr, p_BtM + 4*16384, clsb + 4*128, p_cs, 128, 1);
    head_out_kernel<<<(NN*32 + 255)/256, 256>>>(p_cs, clsoW, clsob, o_out, CC);

    // confidence head
    gemm_bias_act_kernel<<<gemm_grid, 256>>>(h_out, nullptr, p_BtM + 5*16384, cnfb + 0*128, p_hs, 128, 1);
    gemm_bias_act_kernel<<<gemm_grid, 256>>>(p_hs,  nullptr, p_BtM + 6*16384, cnfb + 1*128, p_cs, 128, 1);
    gemm_bias_act_kernel<<<gemm_grid, 256>>>(p_cs,  nullptr, p_BtM + 7*16384, cnfb + 2*128, p_hs, 128, 1);
    gemm_bias_act_kernel<<<gemm_grid, 256>>>(p_hs,  nullptr, p_BtM + 8*16384, cnfb + 3*128, p_cs, 128, 1);
    gemm_bias_act_kernel<<<gemm_grid, 256>>>(p_cs,  nullptr, p_BtM + 9*16384, cnfb + 4*128, p_hs, 128, 1);
    head_out_kernel<<<(NN*32 + 255)/256, 256>>>(p_hs, cnfoW, cnfob, l_out, 1);
}